// round 13
// baseline (speedup 1.0000x reference)
#include <cuda_runtime.h>
#include <cuda_bf16.h>
#include <cuda_fp16.h>
#include <cstdint>

#define BB   8
#define NPTS 2048
#define KNN  32
#define EPS  1e-5f

// ---------------------------------------------------------------------------
// Device scratch (static allocations only — no cudaMalloc allowed)
// ---------------------------------------------------------------------------
__device__ float  g_dot[(long)BB * NPTS * NPTS];
__device__ float  g_sq [(long)BB * NPTS];
__device__ int    g_idx[(long)BB * NPTS * KNN];
__device__ float  g_xc [(long)BB * 192  * NPTS];
__device__ __half g_fth[(long)BB * NPTS * 64];    // fp16 transposed features [b][n][KD]
__device__ float  g_h  [(long)BB * 1024 * NPTS];
__device__ float  g_q  [(long)BB * 1024 * NPTS];
__device__ float  g_k  [(long)BB * 1024 * NPTS];
__device__ float  g_v  [(long)BB * 1024 * NPTS];
__device__ float  g_ff1[(long)BB * 512  * NPTS];

__device__ __forceinline__ uint32_t packh2(float x, float y) {
    __half2 h = __floats2half2_rn(x, y);
    return *(uint32_t*)&h;
}
__device__ __forceinline__ unsigned long long packkey(float v, int m) {
    uint32_t bu = __float_as_uint(v);
    bu ^= ((uint32_t)((int)bu >> 31)) | 0x80000000u;   // monotone sortable map
    return ((unsigned long long)bu << 32) | (uint32_t)m;
}
__device__ __forceinline__ void mma16816(float* c, const uint32_t* a, const uint32_t* b) {
    asm volatile(
        "mma.sync.aligned.m16n8k16.row.col.f32.f16.f16.f32 "
        "{%0,%1,%2,%3}, {%4,%5,%6,%7}, {%8,%9}, {%0,%1,%2,%3};"
        : "+f"(c[0]), "+f"(c[1]), "+f"(c[2]), "+f"(c[3])
        : "r"(a[0]), "r"(a[1]), "r"(a[2]), "r"(a[3]), "r"(b[0]), "r"(b[1]));
}

// ---------------------------------------------------------------------------
// FP16 tensor-core GEMM (m16n8k16, fp32 accumulate), double-buffered (R9 exact)
// epi: 0=none, 1=lrelu, 2=bn(i)+lrelu, 3=bn(acc + resid[i][j])
// ---------------------------------------------------------------------------
__global__ __launch_bounds__(256, 2)
void gemm_f16(const float* __restrict__ A, const float* __restrict__ B,
              float* __restrict__ C,
              int M, int N, int K,
              long laI, long laK, long sA,
              long lbJ, long lbK, long sB,
              long ldc, long sC,
              int epi, const float* __restrict__ bnp,
              const float* __restrict__ resid)
{
    __shared__ uint32_t As[2][8 * 136];
    __shared__ uint32_t Bs[2][8 * 136];

    const int tid  = threadIdx.x;
    const int lane = tid & 31;
    const int w    = tid >> 5;
    const int wm   = w >> 2;
    const int wn   = w & 3;
    const int i0   = blockIdx.y * 128;
    const int j0   = blockIdx.x * 128;

    const float* Ab = A + (long)blockIdx.z * sA;
    const float* Bb = B + (long)blockIdx.z * sB;
    const bool aKf = (laK == 1);
    const bool bKf = (lbK == 1);

    int aiv[4], akp[4], bjv[4], bkp[4];
#pragma unroll
    for (int u = 0; u < 4; u++) {
        int q = u * 256 + tid;
        if (aKf) { akp[u] = q & 7; aiv[u] = q >> 3; }
        else     { akp[u] = q >> 7; aiv[u] = q & 127; }
        if (bKf) { bkp[u] = q & 7; bjv[u] = q >> 3; }
        else     { bkp[u] = q >> 7; bjv[u] = q & 127; }
    }

    float acc[4][4][4];
#pragma unroll
    for (int mi = 0; mi < 4; mi++)
#pragma unroll
        for (int ni = 0; ni < 4; ni++)
#pragma unroll
            for (int r = 0; r < 4; r++) acc[mi][ni][r] = 0.f;

    const int qrow = lane >> 2;
    const int qcol = lane & 3;

    float2 ra[4], rb[4];
    auto stage_load = [&](int kt) {
        const long kb = (long)kt * 16;
#pragma unroll
        for (int u = 0; u < 4; u++) {
            if (aKf) {
                ra[u] = *(const float2*)(Ab + (long)(i0 + aiv[u]) * laI + kb + 2 * akp[u]);
            } else {
                const float* p = Ab + (kb + 2 * akp[u]) * laK + i0 + aiv[u];
                ra[u].x = p[0]; ra[u].y = p[laK];
            }
            if (bKf) {
                rb[u] = *(const float2*)(Bb + (long)(j0 + bjv[u]) * lbJ + kb + 2 * bkp[u]);
            } else {
                const float* p = Bb + (kb + 2 * bkp[u]) * lbK + j0 + bjv[u];
                rb[u].x = p[0]; rb[u].y = p[lbK];
            }
        }
    };
    auto stage_store = [&](int buf) {
#pragma unroll
        for (int u = 0; u < 4; u++) {
            As[buf][akp[u] * 136 + aiv[u]] = packh2(ra[u].x, ra[u].y);
            Bs[buf][bkp[u] * 136 + bjv[u]] = packh2(rb[u].x, rb[u].y);
        }
    };

    stage_load(0);
    stage_store(0);
    __syncthreads();

    const int nkt = K / 16;
    for (int kt = 0; kt < nkt; kt++) {
        const int cur = kt & 1;
        const bool more = (kt + 1 < nkt);
        if (more) stage_load(kt + 1);

        const uint32_t* Ac = As[cur];
        const uint32_t* Bc = Bs[cur];
        uint32_t af[4][4], bf[4][2];
#pragma unroll
        for (int mi = 0; mi < 4; mi++) {
            int m0 = wm * 64 + mi * 16 + qrow;
            af[mi][0] = Ac[qcol * 136 + m0];
            af[mi][1] = Ac[qcol * 136 + m0 + 8];
            af[mi][2] = Ac[(qcol + 4) * 136 + m0];
            af[mi][3] = Ac[(qcol + 4) * 136 + m0 + 8];
        }
#pragma unroll
        for (int ni = 0; ni < 4; ni++) {
            int n0 = wn * 32 + ni * 8 + qrow;
            bf[ni][0] = Bc[qcol * 136 + n0];
            bf[ni][1] = Bc[(qcol + 4) * 136 + n0];
        }
#pragma unroll
        for (int mi = 0; mi < 4; mi++)
#pragma unroll
            for (int ni = 0; ni < 4; ni++)
                mma16816(acc[mi][ni], af[mi], bf[ni]);

        if (more) {
            stage_store(cur ^ 1);
            __syncthreads();
        }
    }

    float* Cb = C + (long)blockIdx.z * sC;
    const float* Rb = resid ? (resid + (long)blockIdx.z * sC) : nullptr;
#pragma unroll
    for (int mi = 0; mi < 4; mi++) {
        int r0 = i0 + wm * 64 + mi * 16 + qrow;
        int r1 = r0 + 8;
        float s0 = 1.f, t0 = 0.f, s1 = 1.f, t1 = 0.f;
        if (epi >= 2) {
            float g = bnp[r0], bb = bnp[M + r0], m = bnp[2 * M + r0], vv = bnp[3 * M + r0];
            s0 = g * rsqrtf(vv + EPS); t0 = bb - m * s0;
            g = bnp[r1]; bb = bnp[M + r1]; m = bnp[2 * M + r1]; vv = bnp[3 * M + r1];
            s1 = g * rsqrtf(vv + EPS); t1 = bb - m * s1;
        }
#pragma unroll
        for (int ni = 0; ni < 4; ni++) {
            int cc = j0 + wn * 32 + ni * 8 + 2 * qcol;
            float y0 = acc[mi][ni][0], y1 = acc[mi][ni][1];
            float y2 = acc[mi][ni][2], y3 = acc[mi][ni][3];
            if (epi == 1) {
                y0 = (y0 >= 0.f) ? y0 : 0.2f * y0;
                y1 = (y1 >= 0.f) ? y1 : 0.2f * y1;
                y2 = (y2 >= 0.f) ? y2 : 0.2f * y2;
                y3 = (y3 >= 0.f) ? y3 : 0.2f * y3;
            } else if (epi == 2) {
                y0 = y0 * s0 + t0; y0 = (y0 >= 0.f) ? y0 : 0.2f * y0;
                y1 = y1 * s0 + t0; y1 = (y1 >= 0.f) ? y1 : 0.2f * y1;
                y2 = y2 * s1 + t1; y2 = (y2 >= 0.f) ? y2 : 0.2f * y2;
                y3 = y3 * s1 + t1; y3 = (y3 >= 0.f) ? y3 : 0.2f * y3;
            } else if (epi == 3) {
                float2 z0 = *(const float2*)(Rb + (long)r0 * ldc + cc);
                float2 z1 = *(const float2*)(Rb + (long)r1 * ldc + cc);
                y0 = (y0 + z0.x) * s0 + t0;
                y1 = (y1 + z0.y) * s0 + t0;
                y2 = (y2 + z1.x) * s1 + t1;
                y3 = (y3 + z1.y) * s1 + t1;
            }
            *(float2*)(Cb + (long)r0 * ldc + cc) = make_float2(y0, y1);
            *(float2*)(Cb + (long)r1 * ldc + cc) = make_float2(y2, y3);
        }
    }
}

// ---------------------------------------------------------------------------
// fp32 SGEMM (kNN dot products — selection is tie-sensitive, stays fp32)
// ---------------------------------------------------------------------------
__global__ void gemm128(const float* __restrict__ A, const float* __restrict__ B,
                        float* __restrict__ C,
                        int M, int N, int K,
                        long laI, long laK, long sA,
                        long lbJ, long lbK, long sB,
                        long ldc, long sC)
{
    __shared__ float4 As4[8 * 33];
    __shared__ float4 Bs4[8 * 33];
    float* As = (float*)As4;
    float* Bs = (float*)Bs4;

    const int tid = threadIdx.x;
    const int tx  = tid & 15;
    const int ty  = tid >> 4;
    const int i0  = blockIdx.y * 128;
    const int j0  = blockIdx.x * 128;

    const float* Ab = A + (long)blockIdx.z * sA;
    const float* Bb = B + (long)blockIdx.z * sB;

    const bool aKfast = (laK == 1);
    const bool bKfast = (lbK == 1);

    float acc[8][8];
#pragma unroll
    for (int r = 0; r < 8; r++)
#pragma unroll
        for (int c = 0; c < 8; c++) acc[r][c] = 0.f;

    for (int k0 = 0; k0 < K; k0 += 8) {
#pragma unroll
        for (int u = 0; u < 4; u++) {
            int l = tid + u * 256;
            int i, k;
            if (aKfast) { i = l >> 3; k = l & 7; }
            else        { i = l & 127; k = l >> 7; }
            int kg = k0 + k;
            float v = 0.f;
            if (kg < K) v = Ab[(long)(i0 + i) * laI + (long)kg * laK];
            As[k * 132 + i] = v;
        }
#pragma unroll
        for (int u = 0; u < 4; u++) {
            int l = tid + u * 256;
            int j, k;
            if (bKfast) { j = l >> 3; k = l & 7; }
            else        { j = l & 127; k = l >> 7; }
            int kg = k0 + k;
            float v = 0.f;
            if (kg < K) v = Bb[(long)(j0 + j) * lbJ + (long)kg * lbK];
            Bs[k * 132 + j] = v;
        }
        __syncthreads();

#pragma unroll
        for (int kk = 0; kk < 8; kk++) {
            const float4* Ar = (const float4*)(As + kk * 132);
            const float4* Br = (const float4*)(Bs + kk * 132);
            float4 a0 = Ar[ty * 2], a1 = Ar[ty * 2 + 1];
            float4 b0 = Br[tx * 2], b1 = Br[tx * 2 + 1];
            float av[8] = {a0.x, a0.y, a0.z, a0.w, a1.x, a1.y, a1.z, a1.w};
            float bv[8] = {b0.x, b0.y, b0.z, b0.w, b1.x, b1.y, b1.z, b1.w};
#pragma unroll
            for (int r = 0; r < 8; r++)
#pragma unroll
                for (int c = 0; c < 8; c++)
                    acc[r][c] += av[r] * bv[c];
        }
        __syncthreads();
    }

    float* Cb = C + (long)blockIdx.z * sC;
#pragma unroll
    for (int r = 0; r < 8; r++) {
        int ig = i0 + ty * 8 + r;
        float4* dst = (float4*)(Cb + (long)ig * ldc + (j0 + tx * 8));
        dst[0] = make_float4(acc[r][0], acc[r][1], acc[r][2], acc[r][3]);
        dst[1] = make_float4(acc[r][4], acc[r][5], acc[r][6], acc[r][7]);
    }
}

// ---------------------------------------------------------------------------
// Squared norm per point
// ---------------------------------------------------------------------------
__global__ void sqnorm_k(const float* __restrict__ f, float* __restrict__ sq,
                         int C, long bstride)
{
    int n = blockIdx.x * blockDim.x + threadIdx.x;
    int b = blockIdx.y;
    if (n >= NPTS) return;
    const float* fb = f + (long)b * bstride;
    float s = 0.f;
    for (int c = 0; c < C; c++) {
        float v = fb[(long)c * NPTS + n];
        s += v * v;
    }
    sq[(long)b * NPTS + n] = s;
}

// ---------------------------------------------------------------------------
// Feature transpose to fp16, zero-padded: fth[b][n][c] = (c<CIN)? f[b][c][n]:0
// ---------------------------------------------------------------------------
__global__ void transpose_h(const float* __restrict__ f, long fBS, int CIN, int KD,
                            __half* __restrict__ fth)
{
    int n = blockIdx.x * 256 + threadIdx.x;
    int c = blockIdx.y, b = blockIdx.z;
    float v = (c < CIN) ? f[(long)b * fBS + (long)c * NPTS + n] : 0.f;
    fth[((long)b * NPTS + n) * KD + c] = __float2half(v);
}

// ---------------------------------------------------------------------------
// Top-K (32 smallest), warp-per-row, smem key cache, float4 build (R12, best)
// ---------------------------------------------------------------------------
__global__ __launch_bounds__(256)
void topk_w(const float* __restrict__ dot, const float* __restrict__ sq,
            int* __restrict__ idx)
{
    extern __shared__ float skey[];
    const int lane = threadIdx.x & 31;
    const int wid  = threadIdx.x >> 5;
    const int n = blockIdx.x * 8 + wid;
    const int b = blockIdx.y;
    float* key = skey + wid * NPTS;
    const float* drow = dot + ((long)b * NPTS + n) * NPTS;
    const float* sqb  = sq + (long)b * NPTS;

    unsigned long long cmin[8];
#pragma unroll
    for (int ch = 0; ch < 8; ch++) cmin[ch] = ~0ull;

#pragma unroll 4
    for (int t16 = 0; t16 < 16; t16++) {
        int m0 = t16 * 128 + lane * 4;
        float4 dv = *(const float4*)(drow + m0);
        float4 sv = *(const float4*)(sqb + m0);
        float v0 = sv.x - 2.f * dv.x;
        float v1 = sv.y - 2.f * dv.y;
        float v2 = sv.z - 2.f * dv.z;
        float v3 = sv.w - 2.f * dv.w;
        *(float4*)(key + m0) = make_float4(v0, v1, v2, v3);
        int ch = t16 >> 1;
        unsigned long long k0 = packkey(v0, m0);
        unsigned long long k1 = packkey(v1, m0 + 1);
        unsigned long long k2 = packkey(v2, m0 + 2);
        unsigned long long k3 = packkey(v3, m0 + 3);
        if (k1 < k0) k0 = k1;
        if (k3 < k2) k2 = k3;
        if (k2 < k0) k0 = k2;
        if (k0 < cmin[ch]) cmin[ch] = k0;
    }
    unsigned long long laneMin = cmin[0];
#pragma unroll
    for (int ch = 1; ch < 8; ch++) if (cmin[ch] < laneMin) laneMin = cmin[ch];

    int* orow = idx + ((long)b * NPTS + n) * KNN;
    for (int it = 0; it < KNN; it++) {
        unsigned long long r = laneMin;
#pragma unroll
        for (int off = 16; off; off >>= 1) {
            unsigned long long o = __shfl_xor_sync(0xffffffffu, r, off);
            if (o < r) r = o;
        }
        int ri = (int)(uint32_t)r;
        if (lane == 0) orow[it] = ri;
        if (lane == ((ri >> 2) & 31)) {
            key[ri] = 3.4e38f;
            int ch = ri >> 8;
            unsigned long long nm = ~0ull;
#pragma unroll
            for (int t2 = 0; t2 < 2; t2++) {
                int m0 = (ch * 2 + t2) * 128 + lane * 4;
                float4 kv = *(const float4*)(key + m0);
                unsigned long long k0 = packkey(kv.x, m0);
                unsigned long long k1 = packkey(kv.y, m0 + 1);
                unsigned long long k2 = packkey(kv.z, m0 + 2);
                unsigned long long k3 = packkey(kv.w, m0 + 3);
                if (k1 < k0) k0 = k1;
                if (k3 < k2) k2 = k3;
                if (k2 < k0) k0 = k2;
                if (k0 < nm) nm = k0;
            }
            cmin[ch] = nm;
            laneMin = cmin[0];
#pragma unroll
            for (int c2 = 1; c2 < 8; c2++) if (cmin[c2] < laneMin) laneMin = cmin[c2];
        }
        __syncwarp();
    }
}

// ---------------------------------------------------------------------------
// Tensor-core EdgeConv v2: 16 points/block, 8 warps (2 points/warp),
// weights staged ONCE per block as fp16 fragments; R8-validated MMA math.
//   L1: H1(32nbr x 64) = E(32 x KD) @ W1a^T + U(ctr), bn1, lrelu (reg repack)
//   L2: H2(32 x 64) = H1 @ W2^T, bn2, lrelu, max over nbr
// ---------------------------------------------------------------------------
template<int CIN, int KD>
__global__ __launch_bounds__(256)
void edgeconv_t2(const float* __restrict__ f, long fBS,
                 const __half* __restrict__ fth,
                 const int* __restrict__ idxg,
                 const float* __restrict__ w1, const float* __restrict__ bn1,
                 const float* __restrict__ w2, const float* __restrict__ bn2,
                 float* __restrict__ out, long oBS)
{
    constexpr int KC = KD / 16;
    extern __shared__ uint32_t smu[];
    uint32_t* W1h = smu;                              // (KD/2)*72 half2 words
    uint32_t* W2h = W1h + (KD / 2) * 72;              // 32*72
    float*    BNs = (float*)(W2h + 32 * 72);          // 256
    float*    CTR = BNs + 256;                        // CIN*16
    float*    US  = CTR + CIN * 16;                   // 16*64
    uint32_t* Esm = (uint32_t*)(US + 1024);           // 8 * (KD/2)*40

    const int tid  = threadIdx.x;
    const int w    = tid >> 5;
    const int lane = tid & 31;
    const int qrow = lane >> 2;
    const int qcol = lane & 3;
    const int n0   = blockIdx.x * 16;
    const int b    = blockIdx.y;
    const float* fb = f + (long)b * fBS;

    // ---- stage weights (fp16 fragments), BN ----
    for (int l = tid; l < (KD / 2) * 64; l += 256) {
        int kp = l >> 6, o = l & 63;
        int c0 = 2 * kp, c1 = 2 * kp + 1;
        float va = (c0 < CIN) ? w1[o * (2 * CIN) + c0] : 0.f;
        float vb = (c1 < CIN) ? w1[o * (2 * CIN) + c1] : 0.f;
        W1h[kp * 72 + o] = packh2(va, vb);
    }
    for (int l = tid; l < 32 * 64; l += 256) {
        int kp = l >> 6, o = l & 63;
        W2h[kp * 72 + o] = packh2(w2[o * 64 + 2 * kp], w2[o * 64 + 2 * kp + 1]);
    }
    if (tid < 64) {
        float g = bn1[tid], bb = bn1[64 + tid], m = bn1[128 + tid], vv = bn1[192 + tid];
        float s = g * rsqrtf(vv + EPS);
        BNs[tid] = s; BNs[64 + tid] = bb - m * s;
        g = bn2[tid]; bb = bn2[64 + tid]; m = bn2[128 + tid]; vv = bn2[192 + tid];
        s = g * rsqrtf(vv + EPS);
        BNs[128 + tid] = s; BNs[192 + tid] = bb - m * s;
    }
    for (int l = tid; l < CIN * 16; l += 256) {
        int c = l >> 4, p = l & 15;
        CTR[c * 16 + p] = fb[(long)c * NPTS + n0 + p];
    }
    __syncthreads();

    // ---- center term U[p][o] (fp32) ----
#pragma unroll
    for (int r = 0; r < 4; r++) {
        int q = tid + 256 * r;
        int p = q >> 6, o = q & 63;
        float a = 0.f;
        for (int c = 0; c < CIN; c++)
            a += (w1[o * (2 * CIN) + CIN + c] - w1[o * (2 * CIN) + c]) * CTR[c * 16 + p];
        US[p * 64 + o] = a;
    }
    __syncthreads();

    uint32_t* E = Esm + w * (KD / 2) * 40;
    float* ob = out + (long)b * oBS;

    for (int pp = 0; pp < 2; pp++) {
        const int p = w * 2 + pp;
        const int n = n0 + p;

        // ---- gather 32 neighbors (coalesced 128B/32B rows) ----
        __syncwarp();
        {
            int id = idxg[((long)b * NPTS + n) * KNN + lane];
            const uint4* src = (const uint4*)(fth + ((long)b * NPTS + id) * KD);
#pragma unroll
            for (int u = 0; u < KD / 8; u++) {
                uint4 v = src[u];
                E[(4 * u + 0) * 40 + lane] = v.x;
                E[(4 * u + 1) * 40 + lane] = v.y;
                E[(4 * u + 2) * 40 + lane] = v.z;
                E[(4 * u + 3) * 40 + lane] = v.w;
            }
        }
        __syncwarp();

        // ---- layer 1 A fragments ----
        uint32_t a1[2][KC][4];
#pragma unroll
        for (int mi = 0; mi < 2; mi++)
#pragma unroll
            for (int kc = 0; kc < KC; kc++) {
                int m = mi * 16 + qrow;
                a1[mi][kc][0] = E[(8 * kc + qcol) * 40 + m];
                a1[mi][kc][1] = E[(8 * kc + qcol) * 40 + m + 8];
                a1[mi][kc][2] = E[(8 * kc + qcol + 4) * 40 + m];
                a1[mi][kc][3] = E[(8 * kc + qcol + 4) * 40 + m + 8];
            }

        float acc1[2][8][4];
#pragma unroll
        for (int mi = 0; mi < 2; mi++)
#pragma unroll
            for (int j = 0; j < 8; j++)
#pragma unroll
                for (int r = 0; r < 4; r++) acc1[mi][j][r] = 0.f;

#pragma unroll
        for (int j = 0; j < 8; j++) {
            uint32_t bf[KC][2];
#pragma unroll
            for (int kc = 0; kc < KC; kc++) {
                bf[kc][0] = W1h[(8 * kc + qcol) * 72 + j * 8 + qrow];
                bf[kc][1] = W1h[(8 * kc + qcol + 4) * 72 + j * 8 + qrow];
            }
#pragma unroll
            for (int mi = 0; mi < 2; mi++)
#pragma unroll
                for (int kc = 0; kc < KC; kc++)
                    mma16816(acc1[mi][j], a1[mi][kc], bf[kc]);
        }

        // ---- epilogue 1: +U, bn1, lrelu; repack into L2 A-fragments ----
        uint32_t a2[2][4][4];
#pragma unroll
        for (int j = 0; j < 8; j++) {
            int col0 = j * 8 + 2 * qcol;
            float u0 = US[p * 64 + col0],   u1 = US[p * 64 + col0 + 1];
            float s0 = BNs[col0],           t0 = BNs[64 + col0];
            float s1 = BNs[col0 + 1],       t1 = BNs[64 + col0 + 1];
            int kc = j >> 1;
#pragma unroll
            for (int mi = 0; mi < 2; mi++) {
                float y0 = (acc1[mi][j][0] + u0) * s0 + t0; y0 = (y0 >= 0.f) ? y0 : 0.2f * y0;
                float y1 = (acc1[mi][j][1] + u1) * s1 + t1; y1 = (y1 >= 0.f) ? y1 : 0.2f * y1;
                float y2 = (acc1[mi][j][2] + u0) * s0 + t0; y2 = (y2 >= 0.f) ? y2 : 0.2f * y2;
                float y3 = (acc1[mi][j][3] + u1) * s1 + t1; y3 = (y3 >= 0.f) ? y3 : 0.2f * y3;
                if (j & 1) { a2[mi][kc][2] = packh2(y0, y1); a2[mi][kc][3] = packh2(y2, y3); }
                else       { a2[mi][kc][0] = packh2(y0, y1); a2[mi][kc][1] = packh2(y2, y3); }
            }
        }

        // ---- layer 2 ----
        float acc2[2][8][4];
#pragma unroll
        for (int mi = 0; mi < 2; mi++)
#pragma unroll
            for (int j = 0; j < 8; j++)
#pragma unroll
                for (int r = 0; r < 4; r++) acc2[mi][j][r] = 0.f;

#pragma unroll
        for (int j = 0; j < 8; j++) {
            uint32_t bf[4][2];
#pragma unroll
            for (int kc = 0; kc < 4; kc++) {
                bf[kc][0] = W2h[(8 * kc + qcol) * 72 + j * 8 + qrow];
                bf[kc][1] = W2h[(8 * kc + qcol + 4) * 72 + j * 8 + qrow];
            }
#pragma unroll
            for (int mi = 0; mi < 2; mi++)
#pragma unroll
                for (int kc = 0; kc < 4; kc++)
                    mma16816(acc2[mi][j], a2[mi][kc], bf[kc]);
        }

        // ---- epilogue 2: bn2, lrelu, max over 32 neighbors, write ----
#pragma unroll
        for (int j = 0; j < 8; j++) {
            int col0 = j * 8 + 2 * qcol;
            float s0 = BNs[128 + col0],     t0 = BNs[192 + col0];
            float s1 = BNs[128 + col0 + 1], t1 = BNs[192 + col0 + 1];
            float m0 = -3.4e38f, m1 = -3.4e38f;
#pragma unroll
            for (int mi = 0; mi < 2; mi++) {
                float y0 = acc2[mi][j][0] * s0 + t0; y0 = (y0 >= 0.f) ? y0 : 0.2f * y0;
                float y1 = acc2[mi][j][1] * s1 + t1; y1 = (y1 >= 0.f) ? y1 : 0.2f * y1;
                float y2 = acc2[mi][j][2] * s0 + t0; y2 = (y2 >= 0.f) ? y2 : 0.2f * y2;
                float y3 = acc2[mi][j][3] * s1 + t1; y3 = (y3 >= 0.f) ? y3 : 0.2f * y3;
                m0 = fmaxf(m0, fmaxf(y0, y2));
                m1 = fmaxf(m1, fmaxf(y1, y3));
            }
#pragma unroll
            for (int off = 4; off <= 16; off <<= 1) {
                m0 = fmaxf(m0, __shfl_xor_sync(0xffffffffu, m0, off));
                m1 = fmaxf(m1, __shfl_xor_sync(0xffffffffu, m1, off));
            }
            if (qrow == 0) {
                ob[(long)col0 * NPTS + n]       = m0;
                ob[(long)(col0 + 1) * NPTS + n] = m1;
            }
        }
    }
}

// ---------------------------------------------------------------------------
// Row softmax, single read + single write (R7, passing)
// ---------------------------------------------------------------------------
__global__ __launch_bounds__(256)
void softmax_s(float* __restrict__ S)
{
    __shared__ float red[8];
    const int tid = threadIdx.x, lane = tid & 31, wid = tid >> 5;
    float* row = S + ((long)blockIdx.y * NPTS + blockIdx.x) * NPTS;
    const float scale = 0.03125f;

    float4 v0 = *(float4*)(row + tid * 8);
    float4 v1 = *(float4*)(row + tid * 8 + 4);
    float mx = fmaxf(fmaxf(fmaxf(v0.x, v0.y), fmaxf(v0.z, v0.w)),
                     fmaxf(fmaxf(v1.x, v1.y), fmaxf(v1.z, v1.w)));
#pragma unroll
    for (int off = 16; off; off >>= 1)
        mx = fmaxf(mx, __shfl_xor_sync(0xffffffffu, mx, off));
    if (lane == 0) red[wid] = mx;
    __syncthreads();
    mx = fmaxf(fmaxf(fmaxf(red[0], red[1]), fmaxf(red[2], red[3])),
               fmaxf(fmaxf(red[4], red[5]), fmaxf(red[6], red[7])));
    __syncthreads();

    v0.x = __expf((v0.x - mx) * scale); v0.y = __expf((v0.y - mx) * scale);
    v0.z = __expf((v0.z - mx) * scale); v0.w = __expf((v0.w - mx) * scale);
    v1.x = __expf((v1.x - mx) * scale); v1.y = __expf((v1.y - mx) * scale);
    v1.z = __expf((v1.z - mx) * scale); v1.w = __expf((v1.w - mx) * scale);
    float sum = v0.x + v0.y + v0.z + v0.w + v1.x + v1.y + v1.z + v1.w;
#pragma unroll
    for (int off = 16; off; off >>= 1)
        sum += __shfl_xor_sync(0xffffffffu, sum, off);
    if (lane == 0) red[wid] = sum;
    __syncthreads();
    sum = red[0] + red[1] + red[2] + red[3] + red[4] + red[5] + red[6] + red[7];
    float inv = 1.f / sum;

    v0.x *= inv; v0.y *= inv; v0.z *= inv; v0.w *= inv;
    v1.x *= inv; v1.y *= inv; v1.z *= inv; v1.w *= inv;
    *(float4*)(row + tid * 8)     = v0;
    *(float4*)(row + tid * 8 + 4) = v1;
}

// ---------------------------------------------------------------------------
// Launch
// ---------------------------------------------------------------------------
static inline int ec2_smem(int cin, int kd) {
    return ((kd / 2) * 72 + 32 * 72) * 4
         + (256 + cin * 16 + 1024) * 4
         + 8 * (kd / 2) * 40 * 4;
}

extern "C" void kernel_launch(void* const* d_in, const int* in_sizes, int n_in,
                              void* d_out, int out_size)
{
    const float* x      = (const float*)d_in[0];
    const float* ec1_w1 = (const float*)d_in[1];
    const float* ec1_b1 = (const float*)d_in[2];
    const float* ec1_w2 = (const float*)d_in[3];
    const float* ec1_b2 = (const float*)d_in[4];
    const float* ec2_w1 = (const float*)d_in[5];
    const float* ec2_b1 = (const float*)d_in[6];
    const float* ec2_w2 = (const float*)d_in[7];
    const float* ec2_b2 = (const float*)d_in[8];
    const float* ec3_w1 = (const float*)d_in[9];
    const float* ec3_b1 = (const float*)d_in[10];
    const float* ec3_w2 = (const float*)d_in[11];
    const float* ec3_b2 = (const float*)d_in[12];
    const float* emb_w  = (const float*)d_in[13];
    const float* q_w    = (const float*)d_in[14];
    const float* k_w    = (const float*)d_in[15];
    const float* v_w    = (const float*)d_in[16];
    const float* attb1  = (const float*)d_in[17];
    const float* ff_w1  = (const float*)d_in[18];
    const float* ff_w2  = (const float*)d_in[19];
    const float* attb2  = (const float*)d_in[20];
    const float* cb_w   = (const float*)d_in[21];
    const float* cb_bn  = (const float*)d_in[22];

    float *p_dot, *p_sq, *p_xc, *p_h, *p_q, *p_k, *p_v, *p_ff1;
    __half* p_fth;
    int* p_idx;
    cudaGetSymbolAddress((void**)&p_dot, g_dot);
    cudaGetSymbolAddress((void**)&p_sq,  g_sq);
    cudaGetSymbolAddress((void**)&p_idx, g_idx);
    cudaGetSymbolAddress((void**)&p_xc,  g_xc);
    cudaGetSymbolAddress((void**)&p_fth, g_fth);
    cudaGetSymbolAddress((void**)&p_h,   g_h);
    cudaGetSymbolAddress((void**)&p_q,   g_q);
    cudaGetSymbolAddress((void**)&p_k,   g_k);
    cudaGetSymbolAddress((void**)&p_v,   g_v);
    cudaGetSymbolAddress((void**)&p_ff1, g_ff1);

    static bool attr_done = false;
    if (!attr_done) {
        cudaFuncSetAttribute(topk_w, cudaFuncAttributeMaxDynamicSharedMemorySize,
                             8 * NPTS * 4);
        cudaFuncSetAttribute(edgeconv_t2<3, 16>,
                             cudaFuncAttributeMaxDynamicSharedMemorySize, ec2_smem(3, 16));
        cudaFuncSetAttribute(edgeconv_t2<64, 64>,
                             cudaFuncAttributeMaxDynamicSharedMemorySize, ec2_smem(64, 64));
        attr_done = true;
    }

    const long NN2 = (long)NPTS * NPTS;
    dim3 gSq(NPTS / 256, BB), bSq(256);
    dim3 gRow(NPTS, BB), bRow(256);
    dim3 gTopk(NPTS / 8, BB);
    dim3 gEc(NPTS / 16, BB);
    const int smemTopk = 8 * NPTS * 4;

    // ---- EdgeConv 1 (CIN=3, KD=16) ----
    sqnorm_k<<<gSq, bSq>>>(x, p_sq, 3, (long)3 * NPTS);
    gemm128<<<dim3(16, 16, BB), 256>>>(x, x, p_dot, NPTS, NPTS, 3,
                                       1, NPTS, (long)3 * NPTS,
                                       1, NPTS, (long)3 * NPTS,
                                       NPTS, NN2);
    transpose_h<<<dim3(NPTS / 256, 16, BB), 256>>>(x, (long)3 * NPTS, 3, 16, p_fth);
    topk_w<<<gTopk, 256, smemTopk>>>(p_dot, p_sq, p_idx);
    edgeconv_t2<3, 16><<<gEc, 256, ec2_smem(3, 16)>>>(x, (long)3 * NPTS, p_fth, p_idx,
                                                      ec1_w1, ec1_b1, ec1_w2, ec1_b2,
                                                      p_xc, (long)192 * NPTS);

    // ---- EdgeConv 2 (CIN=64, KD=64) ----
    sqnorm_k<<<gSq, bSq>>>(p_xc, p_sq, 64, (long)192 * NPTS);
    gemm128<<<dim3(16, 16, BB), 256>>>(p_xc, p_xc, p_dot, NPTS, NPTS, 64,
                                       1, NPTS, (long)192 * NPTS,
                                       1, NPTS, (long)192 * NPTS,
                                       NPTS, NN2);
    transpose_h<<<dim3(NPTS / 256, 64, BB), 256>>>(p_xc, (long)192 * NPTS, 64, 64, p_fth);
    topk_w<<<gTopk, 256, smemTopk>>>(p_dot, p_sq, p_idx);
    edgeconv_t2<64, 64><<<gEc, 256, ec2_smem(64, 64)>>>(p_xc, (long)192 * NPTS, p_fth, p_idx,
                                                        ec2_w1, ec2_b1, ec2_w2, ec2_b2,
                                                        p_xc + (long)64 * NPTS,
                                                        (long)192 * NPTS);

    // ---- EdgeConv 3 (CIN=64, KD=64) ----
    sqnorm_k<<<gSq, bSq>>>(p_xc + (long)64 * NPTS, p_sq, 64, (long)192 * NPTS);
    gemm128<<<dim3(16, 16, BB), 256>>>(p_xc + (long)64 * NPTS, p_xc + (long)64 * NPTS,
                                       p_dot, NPTS, NPTS, 64,
                                       1, NPTS, (long)192 * NPTS,
                                       1, NPTS, (long)192 * NPTS,
                                       NPTS, NN2);
    transpose_h<<<dim3(NPTS / 256, 64, BB), 256>>>(p_xc + (long)64 * NPTS,
                                                   (long)192 * NPTS, 64, 64, p_fth);
    topk_w<<<gTopk, 256, smemTopk>>>(p_dot, p_sq, p_idx);
    edgeconv_t2<64, 64><<<gEc, 256, ec2_smem(64, 64)>>>(p_xc + (long)64 * NPTS,
                                                        (long)192 * NPTS, p_fth, p_idx,
                                                        ec3_w1, ec3_b1, ec3_w2, ec3_b2,
                                                        p_xc + (long)128 * NPTS,
                                                        (long)192 * NPTS);

    // ---- emb: h = emb_w (1024x192) @ xc ----
    gemm_f16<<<dim3(16, 8, BB), 256>>>(emb_w, p_xc, p_h, 1024, NPTS, 192,
                                       192, 1, 0,
                                       1, NPTS, (long)192 * NPTS,
                                       NPTS, (long)1024 * NPTS, 0, nullptr, nullptr);

    // ---- q, k, v ----
    gemm_f16<<<dim3(16, 8, BB), 256>>>(q_w, p_h, p_q, 1024, NPTS, 1024,
                                       1024, 1, 0,
                                       1, NPTS, (long)1024 * NPTS,
                                       NPTS, (long)1024 * NPTS, 0, nullptr, nullptr);
    gemm_f16<<<dim3(16, 8, BB), 256>>>(k_w, p_h, p_k, 1024, NPTS, 1024,
                                       1024, 1, 0,
                                       1, NPTS, (long)1024 * NPTS,
                                       NPTS, (long)1024 * NPTS, 0, nullptr, nullptr);
    gemm_f16<<<dim3(16, 8, BB), 256>>>(v_w, p_h, p_v, 1024, NPTS, 1024,
                                       1024, 1, 0,
                                       1, NPTS, (long)1024 * NPTS,
                                       NPTS, (long)1024 * NPTS, 0, nullptr, nullptr);

    // ---- scores = q^T k ----
    gemm_f16<<<dim3(16, 16, BB), 256>>>(p_q, p_k, p_dot, NPTS, NPTS, 1024,
                                        1, NPTS, (long)1024 * NPTS,
                                        1, NPTS, (long)1024 * NPTS,
                                        NPTS, NN2, 0, nullptr, nullptr);
    softmax_s<<<gRow, bRow>>>(p_dot);

    // ---- h = bn(h + att @ v, att_bn1) ----
    gemm_f16<<<dim3(16, 8, BB), 256>>>(p_v, p_dot, p_h, 1024, NPTS, NPTS,
                                       NPTS, 1, (long)1024 * NPTS,
                                       NPTS, 1, NN2,
                                       NPTS, (long)1024 * NPTS, 3, attb1, p_h);

    // ---- ff1 = lrelu(ff_w1 @ h) ----
    gemm_f16<<<dim3(16, 4, BB), 256>>>(ff_w1, p_h, p_ff1, 512, NPTS, 1024,
                                       1024, 1, 0,
                                       1, NPTS, (long)1024 * NPTS,
                                       NPTS, (long)512 * NPTS, 1, nullptr, nullptr);

    // ---- h = bn(h + ff_w2 @ ff1, att_bn2) ----
    gemm_f16<<<dim3(16, 8, BB), 256>>>(ff_w2, p_ff1, p_h, 1024, NPTS, 512,
                                       512, 1, 0,
                                       1, NPTS, (long)512 * NPTS,
                                       NPTS, (long)1024 * NPTS, 3, attb2, p_h);

    // ---- out = lrelu(bn(cb_w @ h, cb_bn)) -> d_out ----
    gemm_f16<<<dim3(16, 8, BB), 256>>>(cb_w, p_h, (float*)d_out, 1024, NPTS, 1024,
                                       1024, 1, 0,
                                       1, NPTS, (long)1024 * NPTS,
                                       NPTS, (long)1024 * NPTS, 2, cb_bn, nullptr);
}

// round 15
// speedup vs baseline: 1.0150x; 1.0150x over previous
#include <cuda_runtime.h>
#include <cuda_bf16.h>
#include <cuda_fp16.h>
#include <cstdint>

#define BB   8
#define NPTS 2048
#define KNN  32
#define EPS  1e-5f

// ---------------------------------------------------------------------------
// Device scratch (static allocations only — no cudaMalloc allowed)
// ---------------------------------------------------------------------------
__device__ float g_dot[(long)BB * NPTS * NPTS];
__device__ float g_sq [(long)BB * NPTS];
__device__ int   g_idx[(long)BB * NPTS * KNN];
__device__ float g_xc [(long)BB * 192  * NPTS];
__device__ float g_ft [(long)BB * NPTS * 64];
__device__ float g_h  [(long)BB * 1024 * NPTS];
__device__ float g_q  [(long)BB * 1024 * NPTS];
__device__ float g_k  [(long)BB * 1024 * NPTS];
__device__ float g_v  [(long)BB * 1024 * NPTS];
__device__ float g_ff1[(long)BB * 512  * NPTS];

__device__ __forceinline__ uint32_t packh2(float x, float y) {
    __half2 h = __floats2half2_rn(x, y);
    return *(uint32_t*)&h;
}
__device__ __forceinline__ unsigned long long packkey(float v, int m) {
    uint32_t bu = __float_as_uint(v);
    bu ^= ((uint32_t)((int)bu >> 31)) | 0x80000000u;   // monotone sortable map
    return ((unsigned long long)bu << 32) | (uint32_t)m;
}

// ---------------------------------------------------------------------------
// FP16 tensor-core GEMM (m16n8k16, fp32 accumulate), double-buffered (R9 exact)
// epi: 0=none, 1=lrelu, 2=bn(i)+lrelu, 3=bn(acc + resid[i][j])
// ---------------------------------------------------------------------------
__global__ __launch_bounds__(256, 2)
void gemm_f16(const float* __restrict__ A, const float* __restrict__ B,
              float* __restrict__ C,
              int M, int N, int K,
              long laI, long laK, long sA,
              long lbJ, long lbK, long sB,
              long ldc, long sC,
              int epi, const float* __restrict__ bnp,
              const float* __restrict__ resid)
{
    __shared__ uint32_t As[2][8 * 136];
    __shared__ uint32_t Bs[2][8 * 136];

    const int tid  = threadIdx.x;
    const int lane = tid & 31;
    const int w    = tid >> 5;
    const int wm   = w >> 2;
    const int wn   = w & 3;
    const int i0   = blockIdx.y * 128;
    const int j0   = blockIdx.x * 128;

    const float* Ab = A + (long)blockIdx.z * sA;
    const float* Bb = B + (long)blockIdx.z * sB;
    const bool aKf = (laK == 1);
    const bool bKf = (lbK == 1);

    int aiv[4], akp[4], bjv[4], bkp[4];
#pragma unroll
    for (int u = 0; u < 4; u++) {
        int q = u * 256 + tid;
        if (aKf) { akp[u] = q & 7; aiv[u] = q >> 3; }
        else     { akp[u] = q >> 7; aiv[u] = q & 127; }
        if (bKf) { bkp[u] = q & 7; bjv[u] = q >> 3; }
        else     { bkp[u] = q >> 7; bjv[u] = q & 127; }
    }

    float acc[4][4][4];
#pragma unroll
    for (int mi = 0; mi < 4; mi++)
#pragma unroll
        for (int ni = 0; ni < 4; ni++)
#pragma unroll
            for (int r = 0; r < 4; r++) acc[mi][ni][r] = 0.f;

    const int qrow = lane >> 2;
    const int qcol = lane & 3;

    float2 ra[4], rb[4];
    auto stage_load = [&](int kt) {
        const long kb = (long)kt * 16;
#pragma unroll
        for (int u = 0; u < 4; u++) {
            if (aKf) {
                ra[u] = *(const float2*)(Ab + (long)(i0 + aiv[u]) * laI + kb + 2 * akp[u]);
            } else {
                const float* p = Ab + (kb + 2 * akp[u]) * laK + i0 + aiv[u];
                ra[u].x = p[0]; ra[u].y = p[laK];
            }
            if (bKf) {
                rb[u] = *(const float2*)(Bb + (long)(j0 + bjv[u]) * lbJ + kb + 2 * bkp[u]);
            } else {
                const float* p = Bb + (kb + 2 * bkp[u]) * lbK + j0 + bjv[u];
                rb[u].x = p[0]; rb[u].y = p[lbK];
            }
        }
    };
    auto stage_store = [&](int buf) {
#pragma unroll
        for (int u = 0; u < 4; u++) {
            As[buf][akp[u] * 136 + aiv[u]] = packh2(ra[u].x, ra[u].y);
            Bs[buf][bkp[u] * 136 + bjv[u]] = packh2(rb[u].x, rb[u].y);
        }
    };

    stage_load(0);
    stage_store(0);
    __syncthreads();

    const int nkt = K / 16;
    for (int kt = 0; kt < nkt; kt++) {
        const int cur = kt & 1;
        const bool more = (kt + 1 < nkt);
        if (more) stage_load(kt + 1);

        const uint32_t* Ac = As[cur];
        const uint32_t* Bc = Bs[cur];
        uint32_t af[4][4], bf[4][2];
#pragma unroll
        for (int mi = 0; mi < 4; mi++) {
            int m0 = wm * 64 + mi * 16 + qrow;
            af[mi][0] = Ac[qcol * 136 + m0];
            af[mi][1] = Ac[qcol * 136 + m0 + 8];
            af[mi][2] = Ac[(qcol + 4) * 136 + m0];
            af[mi][3] = Ac[(qcol + 4) * 136 + m0 + 8];
        }
#pragma unroll
        for (int ni = 0; ni < 4; ni++) {
            int n0 = wn * 32 + ni * 8 + qrow;
            bf[ni][0] = Bc[qcol * 136 + n0];
            bf[ni][1] = Bc[(qcol + 4) * 136 + n0];
        }
#pragma unroll
        for (int mi = 0; mi < 4; mi++)
#pragma unroll
            for (int ni = 0; ni < 4; ni++) {
                asm volatile(
                    "mma.sync.aligned.m16n8k16.row.col.f32.f16.f16.f32 "
                    "{%0,%1,%2,%3}, {%4,%5,%6,%7}, {%8,%9}, {%0,%1,%2,%3};"
                    : "+f"(acc[mi][ni][0]), "+f"(acc[mi][ni][1]),
                      "+f"(acc[mi][ni][2]), "+f"(acc[mi][ni][3])
                    : "r"(af[mi][0]), "r"(af[mi][1]), "r"(af[mi][2]), "r"(af[mi][3]),
                      "r"(bf[ni][0]), "r"(bf[ni][1]));
            }

        if (more) {
            stage_store(cur ^ 1);
            __syncthreads();
        }
    }

    float* Cb = C + (long)blockIdx.z * sC;
    const float* Rb = resid ? (resid + (long)blockIdx.z * sC) : nullptr;
#pragma unroll
    for (int mi = 0; mi < 4; mi++) {
        int r0 = i0 + wm * 64 + mi * 16 + qrow;
        int r1 = r0 + 8;
        float s0 = 1.f, t0 = 0.f, s1 = 1.f, t1 = 0.f;
        if (epi >= 2) {
            float g = bnp[r0], bb = bnp[M + r0], m = bnp[2 * M + r0], vv = bnp[3 * M + r0];
            s0 = g * rsqrtf(vv + EPS); t0 = bb - m * s0;
            g = bnp[r1]; bb = bnp[M + r1]; m = bnp[2 * M + r1]; vv = bnp[3 * M + r1];
            s1 = g * rsqrtf(vv + EPS); t1 = bb - m * s1;
        }
#pragma unroll
        for (int ni = 0; ni < 4; ni++) {
            int cc = j0 + wn * 32 + ni * 8 + 2 * qcol;
            float y0 = acc[mi][ni][0], y1 = acc[mi][ni][1];
            float y2 = acc[mi][ni][2], y3 = acc[mi][ni][3];
            if (epi == 1) {
                y0 = (y0 >= 0.f) ? y0 : 0.2f * y0;
                y1 = (y1 >= 0.f) ? y1 : 0.2f * y1;
                y2 = (y2 >= 0.f) ? y2 : 0.2f * y2;
                y3 = (y3 >= 0.f) ? y3 : 0.2f * y3;
            } else if (epi == 2) {
                y0 = y0 * s0 + t0; y0 = (y0 >= 0.f) ? y0 : 0.2f * y0;
                y1 = y1 * s0 + t0; y1 = (y1 >= 0.f) ? y1 : 0.2f * y1;
                y2 = y2 * s1 + t1; y2 = (y2 >= 0.f) ? y2 : 0.2f * y2;
                y3 = y3 * s1 + t1; y3 = (y3 >= 0.f) ? y3 : 0.2f * y3;
            } else if (epi == 3) {
                float2 z0 = *(const float2*)(Rb + (long)r0 * ldc + cc);
                float2 z1 = *(const float2*)(Rb + (long)r1 * ldc + cc);
                y0 = (y0 + z0.x) * s0 + t0;
                y1 = (y1 + z0.y) * s0 + t0;
                y2 = (y2 + z1.x) * s1 + t1;
                y3 = (y3 + z1.y) * s1 + t1;
            }
            *(float2*)(Cb + (long)r0 * ldc + cc) = make_float2(y0, y1);
            *(float2*)(Cb + (long)r1 * ldc + cc) = make_float2(y2, y3);
        }
    }
}

// ---------------------------------------------------------------------------
// fp32 SGEMM (kNN dot products — selection is tie-sensitive, stays fp32)
// ---------------------------------------------------------------------------
__global__ void gemm128(const float* __restrict__ A, const float* __restrict__ B,
                        float* __restrict__ C,
                        int M, int N, int K,
                        long laI, long laK, long sA,
                        long lbJ, long lbK, long sB,
                        long ldc, long sC)
{
    __shared__ float4 As4[8 * 33];
    __shared__ float4 Bs4[8 * 33];
    float* As = (float*)As4;
    float* Bs = (float*)Bs4;

    const int tid = threadIdx.x;
    const int tx  = tid & 15;
    const int ty  = tid >> 4;
    const int i0  = blockIdx.y * 128;
    const int j0  = blockIdx.x * 128;

    const float* Ab = A + (long)blockIdx.z * sA;
    const float* Bb = B + (long)blockIdx.z * sB;

    const bool aKfast = (laK == 1);
    const bool bKfast = (lbK == 1);

    float acc[8][8];
#pragma unroll
    for (int r = 0; r < 8; r++)
#pragma unroll
        for (int c = 0; c < 8; c++) acc[r][c] = 0.f;

    for (int k0 = 0; k0 < K; k0 += 8) {
#pragma unroll
        for (int u = 0; u < 4; u++) {
            int l = tid + u * 256;
            int i, k;
            if (aKfast) { i = l >> 3; k = l & 7; }
            else        { i = l & 127; k = l >> 7; }
            int kg = k0 + k;
            float v = 0.f;
            if (kg < K) v = Ab[(long)(i0 + i) * laI + (long)kg * laK];
            As[k * 132 + i] = v;
        }
#pragma unroll
        for (int u = 0; u < 4; u++) {
            int l = tid + u * 256;
            int j, k;
            if (bKfast) { j = l >> 3; k = l & 7; }
            else        { j = l & 127; k = l >> 7; }
            int kg = k0 + k;
            float v = 0.f;
            if (kg < K) v = Bb[(long)(j0 + j) * lbJ + (long)kg * lbK];
            Bs[k * 132 + j] = v;
        }
        __syncthreads();

#pragma unroll
        for (int kk = 0; kk < 8; kk++) {
            const float4* Ar = (const float4*)(As + kk * 132);
            const float4* Br = (const float4*)(Bs + kk * 132);
            float4 a0 = Ar[ty * 2], a1 = Ar[ty * 2 + 1];
            float4 b0 = Br[tx * 2], b1 = Br[tx * 2 + 1];
            float av[8] = {a0.x, a0.y, a0.z, a0.w, a1.x, a1.y, a1.z, a1.w};
            float bv[8] = {b0.x, b0.y, b0.z, b0.w, b1.x, b1.y, b1.z, b1.w};
#pragma unroll
            for (int r = 0; r < 8; r++)
#pragma unroll
                for (int c = 0; c < 8; c++)
                    acc[r][c] += av[r] * bv[c];
        }
        __syncthreads();
    }

    float* Cb = C + (long)blockIdx.z * sC;
#pragma unroll
    for (int r = 0; r < 8; r++) {
        int ig = i0 + ty * 8 + r;
        float4* dst = (float4*)(Cb + (long)ig * ldc + (j0 + tx * 8));
        dst[0] = make_float4(acc[r][0], acc[r][1], acc[r][2], acc[r][3]);
        dst[1] = make_float4(acc[r][4], acc[r][5], acc[r][6], acc[r][7]);
    }
}

// ---------------------------------------------------------------------------
// Squared norm per point
// ---------------------------------------------------------------------------
__global__ void sqnorm_k(const float* __restrict__ f, float* __restrict__ sq,
                         int C, long bstride)
{
    int n = blockIdx.x * blockDim.x + threadIdx.x;
    int b = blockIdx.y;
    if (n >= NPTS) return;
    const float* fb = f + (long)b * bstride;
    float s = 0.f;
    for (int c = 0; c < C; c++) {
        float v = fb[(long)c * NPTS + n];
        s += v * v;
    }
    sq[(long)b * NPTS + n] = s;
}

// ---------------------------------------------------------------------------
// Feature transpose: ft[b][n][c] = f[b][c][n]  (only for 3-ch layer-1 input)
// ---------------------------------------------------------------------------
__global__ void transpose_k(const float* __restrict__ f, long fBS, int C,
                            float* __restrict__ ft)
{
    int n = blockIdx.x * 256 + threadIdx.x;
    int c = blockIdx.y, b = blockIdx.z;
    ft[((long)b * NPTS + n) * C + c] = f[(long)b * fBS + (long)c * NPTS + n];
}

// ---------------------------------------------------------------------------
// Top-K (32 smallest), warp-per-row, smem key cache, float4 build (R12, best)
// ---------------------------------------------------------------------------
__global__ __launch_bounds__(256)
void topk_w(const float* __restrict__ dot, const float* __restrict__ sq,
            int* __restrict__ idx)
{
    extern __shared__ float skey[];
    const int lane = threadIdx.x & 31;
    const int wid  = threadIdx.x >> 5;
    const int n = blockIdx.x * 8 + wid;
    const int b = blockIdx.y;
    float* key = skey + wid * NPTS;
    const float* drow = dot + ((long)b * NPTS + n) * NPTS;
    const float* sqb  = sq + (long)b * NPTS;

    unsigned long long cmin[8];
#pragma unroll
    for (int ch = 0; ch < 8; ch++) cmin[ch] = ~0ull;

#pragma unroll 4
    for (int t16 = 0; t16 < 16; t16++) {
        int m0 = t16 * 128 + lane * 4;
        float4 dv = *(const float4*)(drow + m0);
        float4 sv = *(const float4*)(sqb + m0);
        float v0 = sv.x - 2.f * dv.x;
        float v1 = sv.y - 2.f * dv.y;
        float v2 = sv.z - 2.f * dv.z;
        float v3 = sv.w - 2.f * dv.w;
        *(float4*)(key + m0) = make_float4(v0, v1, v2, v3);
        int ch = t16 >> 1;
        unsigned long long k0 = packkey(v0, m0);
        unsigned long long k1 = packkey(v1, m0 + 1);
        unsigned long long k2 = packkey(v2, m0 + 2);
        unsigned long long k3 = packkey(v3, m0 + 3);
        if (k1 < k0) k0 = k1;
        if (k3 < k2) k2 = k3;
        if (k2 < k0) k0 = k2;
        if (k0 < cmin[ch]) cmin[ch] = k0;
    }
    unsigned long long laneMin = cmin[0];
#pragma unroll
    for (int ch = 1; ch < 8; ch++) if (cmin[ch] < laneMin) laneMin = cmin[ch];

    int* orow = idx + ((long)b * NPTS + n) * KNN;
    for (int it = 0; it < KNN; it++) {
        unsigned long long r = laneMin;
#pragma unroll
        for (int off = 16; off; off >>= 1) {
            unsigned long long o = __shfl_xor_sync(0xffffffffu, r, off);
            if (o < r) r = o;
        }
        int ri = (int)(uint32_t)r;
        if (lane == 0) orow[it] = ri;
        if (lane == ((ri >> 2) & 31)) {
            key[ri] = 3.4e38f;
            int ch = ri >> 8;
            unsigned long long nm = ~0ull;
#pragma unroll
            for (int t2 = 0; t2 < 2; t2++) {
                int m0 = (ch * 2 + t2) * 128 + lane * 4;
                float4 kv = *(const float4*)(key + m0);
                unsigned long long k0 = packkey(kv.x, m0);
                unsigned long long k1 = packkey(kv.y, m0 + 1);
                unsigned long long k2 = packkey(kv.z, m0 + 2);
                unsigned long long k3 = packkey(kv.w, m0 + 3);
                if (k1 < k0) k0 = k1;
                if (k3 < k2) k2 = k3;
                if (k2 < k0) k0 = k2;
                if (k0 < nm) nm = k0;
            }
            cmin[ch] = nm;
            laneMin = cmin[0];
#pragma unroll
            for (int c2 = 1; c2 < 8; c2++) if (cmin[c2] < laneMin) laneMin = cmin[c2];
        }
        __syncwarp();
    }
}

// ---------------------------------------------------------------------------
// Fused EdgeConv, 16 points/block (R12) + optional dual-write of outputs into
// a DISJOINT point-major ft buffer (feeds next edgeconv; kills transposes).
// ---------------------------------------------------------------------------
template<int CIN>
__global__ __launch_bounds__(256)
void edgeconv_p(const float* __restrict__ f, long fBS,
                const float* __restrict__ ft,
                const int* __restrict__ idxg,
                const float* __restrict__ w1, const float* __restrict__ bn1,
                const float* __restrict__ w2, const float* __restrict__ bn2,
                float* __restrict__ out, long oBS,
                float* __restrict__ ftOut)
{
    constexpr int CP = CIN + 1;
    extern __shared__ float sm[];
    float* W1A  = sm;
    float* W1D  = W1A + CIN * 64;
    float* W2S  = W1D + CIN * 64;
    float* BN   = W2S + 4096;
    float* CTR  = BN + 256;
    float* US   = CTR + CIN * 16;
    int*   IDS  = (int*)(US + 1024);
    float* BUFA = (float*)(IDS + 512);
    float* BUFH = BUFA + 2 * 32 * CP;

    const int tid = threadIdx.x;
    const int n0 = blockIdx.x * 16;
    const int b  = blockIdx.y;
    const float* fb  = f + (long)b * fBS;
    const float* ftb = ft + (long)b * NPTS * CIN;

    for (int l = tid; l < CIN * 64; l += 256) {
        int o = l & 63, c = l >> 6;
        float a = w1[o * (2 * CIN) + c];
        W1A[c * 64 + o] = a;
        W1D[c * 64 + o] = w1[o * (2 * CIN) + CIN + c] - a;
    }
    for (int l = tid; l < 4096; l += 256) {
        int o = l & 63, c = l >> 6;
        W2S[c * 64 + o] = w2[o * 64 + c];
    }
    if (tid < 64) {
        float g = bn1[tid], bb = bn1[64 + tid], m = bn1[128 + tid], vv = bn1[192 + tid];
        float s = g * rsqrtf(vv + EPS);
        BN[tid] = s; BN[64 + tid] = bb - m * s;
        g = bn2[tid]; bb = bn2[64 + tid]; m = bn2[128 + tid]; vv = bn2[192 + tid];
        s = g * rsqrtf(vv + EPS);
        BN[128 + tid] = s; BN[192 + tid] = bb - m * s;
    }
    for (int l = tid; l < CIN * 16; l += 256) {
        int c = l >> 4, p = l & 15;
        CTR[c * 16 + p] = fb[(long)c * NPTS + n0 + p];
    }
    for (int l = tid; l < 512; l += 256)
        IDS[l] = idxg[((long)b * NPTS + n0 + (l >> 5)) * KNN + (l & 31)];
    __syncthreads();

#pragma unroll
    for (int r = 0; r < 4; r++) {
        int q = tid + 256 * r;
        int p = q >> 6, o = q & 63;
        float a = 0.f;
        for (int c = 0; c < CIN; c++)
            a += W1D[c * 64 + o] * CTR[c * 16 + p];
        US[p * 64 + o] = a;
    }

    auto gather = [&](int p, int buf) {
        float* dst = BUFA + buf * 32 * CP;
        if (CIN == 64) {
            for (int l = tid; l < 2048; l += 256) {
                int k = l >> 6, c = l & 63;
                dst[k * CP + c] = ftb[(long)IDS[p * 32 + k] * 64 + c];
            }
        } else {
            for (int l = tid; l < 32 * CIN; l += 256) {
                int k = l / CIN, c = l % CIN;
                dst[k * CP + c] = ftb[(long)IDS[p * 32 + k] * CIN + c];
            }
        }
    };
    gather(0, 0);
    __syncthreads();

    const int k  = tid & 31;
    const int og = tid >> 5;
    float* ob = out + (long)b * oBS;
    float* fo = ftOut ? (ftOut + (long)b * NPTS * 64) : nullptr;

    for (int p = 0; p < 16; p++) {
        const int cur = p & 1;
        const float* A = BUFA + cur * 32 * CP + k * CP;

        float acc[8];
#pragma unroll
        for (int j = 0; j < 8; j++) acc[j] = 0.f;
        for (int c = 0; c < CIN; c++) {
            float nv = A[c];
#pragma unroll
            for (int j = 0; j < 8; j++)
                acc[j] += W1A[c * 64 + og * 8 + j] * nv;
        }
#pragma unroll
        for (int j = 0; j < 8; j++) {
            int o = og * 8 + j;
            float y = (acc[j] + US[p * 64 + o]) * BN[o] + BN[64 + o];
            BUFH[k * 65 + o] = (y >= 0.f) ? y : 0.2f * y;
        }
        if (p + 1 < 16) gather(p + 1, cur ^ 1);
        __syncthreads();

        float acc2[8];
#pragma unroll
        for (int j = 0; j < 8; j++) acc2[j] = 0.f;
        for (int c = 0; c < 64; c++) {
            float hv = BUFH[k * 65 + c];
#pragma unroll
            for (int j = 0; j < 8; j++)
                acc2[j] += W2S[c * 64 + og * 8 + j] * hv;
        }
        float yout[8];
#pragma unroll
        for (int j = 0; j < 8; j++) {
            int o = og * 8 + j;
            float y = acc2[j] * BN[128 + o] + BN[192 + o];
            y = (y >= 0.f) ? y : 0.2f * y;
#pragma unroll
            for (int off = 16; off; off >>= 1)
                y = fmaxf(y, __shfl_xor_sync(0xffffffffu, y, off));
            yout[j] = y;
            if (k == 0) ob[(long)o * NPTS + n0 + p] = y;
        }
        if (fo && k == 0) {
            float4* dst = (float4*)(fo + (long)(n0 + p) * 64 + og * 8);
            dst[0] = make_float4(yout[0], yout[1], yout[2], yout[3]);
            dst[1] = make_float4(yout[4], yout[5], yout[6], yout[7]);
        }
        __syncthreads();
    }
}

// ---------------------------------------------------------------------------
// Row softmax, single read + single write (R7, passing)
// ---------------------------------------------------------------------------
__global__ __launch_bounds__(256)
void softmax_s(float* __restrict__ S)
{
    __shared__ float red[8];
    const int tid = threadIdx.x, lane = tid & 31, wid = tid >> 5;
    float* row = S + ((long)blockIdx.y * NPTS + blockIdx.x) * NPTS;
    const float scale = 0.03125f;

    float4 v0 = *(float4*)(row + tid * 8);
    float4 v1 = *(float4*)(row + tid * 8 + 4);
    float mx = fmaxf(fmaxf(fmaxf(v0.x, v0.y), fmaxf(v0.z, v0.w)),
                     fmaxf(fmaxf(v1.x, v1.y), fmaxf(v1.z, v1.w)));
#pragma unroll
    for (int off = 16; off; off >>= 1)
        mx = fmaxf(mx, __shfl_xor_sync(0xffffffffu, mx, off));
    if (lane == 0) red[wid] = mx;
    __syncthreads();
    mx = fmaxf(fmaxf(fmaxf(red[0], red[1]), fmaxf(red[2], red[3])),
               fmaxf(fmaxf(red[4], red[5]), fmaxf(red[6], red[7])));
    __syncthreads();

    v0.x = __expf((v0.x - mx) * scale); v0.y = __expf((v0.y - mx) * scale);
    v0.z = __expf((v0.z - mx) * scale); v0.w = __expf((v0.w - mx) * scale);
    v1.x = __expf((v1.x - mx) * scale); v1.y = __expf((v1.y - mx) * scale);
    v1.z = __expf((v1.z - mx) * scale); v1.w = __expf((v1.w - mx) * scale);
    float sum = v0.x + v0.y + v0.z + v0.w + v1.x + v1.y + v1.z + v1.w;
#pragma unroll
    for (int off = 16; off; off >>= 1)
        sum += __shfl_xor_sync(0xffffffffu, sum, off);
    if (lane == 0) red[wid] = sum;
    __syncthreads();
    sum = red[0] + red[1] + red[2] + red[3] + red[4] + red[5] + red[6] + red[7];
    float inv = 1.f / sum;

    v0.x *= inv; v0.y *= inv; v0.z *= inv; v0.w *= inv;
    v1.x *= inv; v1.y *= inv; v1.z *= inv; v1.w *= inv;
    *(float4*)(row + tid * 8)     = v0;
    *(float4*)(row + tid * 8 + 4) = v1;
}

// ---------------------------------------------------------------------------
// Launch
// ---------------------------------------------------------------------------
static inline int ec_smem(int cin) {
    return (2 * cin * 64 + 4096 + 256 + cin * 16 + 1024) * 4
         + 512 * 4
         + (2 * 32 * (cin + 1) + 32 * 65) * 4;
}

extern "C" void kernel_launch(void* const* d_in, const int* in_sizes, int n_in,
                              void* d_out, int out_size)
{
    const float* x      = (const float*)d_in[0];
    const float* ec1_w1 = (const float*)d_in[1];
    const float* ec1_b1 = (const float*)d_in[2];
    const float* ec1_w2 = (const float*)d_in[3];
    const float* ec1_b2 = (const float*)d_in[4];
    const float* ec2_w1 = (const float*)d_in[5];
    const float* ec2_b1 = (const float*)d_in[6];
    const float* ec2_w2 = (const float*)d_in[7];
    const float* ec2_b2 = (const float*)d_in[8];
    const float* ec3_w1 = (const float*)d_in[9];
    const float* ec3_b1 = (const float*)d_in[10];
    const float* ec3_w2 = (const float*)d_in[11];
    const float* ec3_b2 = (const float*)d_in[12];
    const float* emb_w  = (const float*)d_in[13];
    const float* q_w    = (const float*)d_in[14];
    const float* k_w    = (const float*)d_in[15];
    const float* v_w    = (const float*)d_in[16];
    const float* attb1  = (const float*)d_in[17];
    const float* ff_w1  = (const float*)d_in[18];
    const float* ff_w2  = (const float*)d_in[19];
    const float* attb2  = (const float*)d_in[20];
    const float* cb_w   = (const float*)d_in[21];
    const float* cb_bn  = (const float*)d_in[22];

    float *p_dot, *p_sq, *p_xc, *p_ft, *p_h, *p_q, *p_k, *p_v, *p_ff1;
    int* p_idx;
    cudaGetSymbolAddress((void**)&p_dot, g_dot);
    cudaGetSymbolAddress((void**)&p_sq,  g_sq);
    cudaGetSymbolAddress((void**)&p_idx, g_idx);
    cudaGetSymbolAddress((void**)&p_xc,  g_xc);
    cudaGetSymbolAddress((void**)&p_ft,  g_ft);
    cudaGetSymbolAddress((void**)&p_h,   g_h);
    cudaGetSymbolAddress((void**)&p_q,   g_q);
    cudaGetSymbolAddress((void**)&p_k,   g_k);
    cudaGetSymbolAddress((void**)&p_v,   g_v);
    cudaGetSymbolAddress((void**)&p_ff1, g_ff1);

    // disjoint point-major feature slabs carved from g_h (emb overwrites later)
    float* ft64_a = p_h;
    float* ft64_b = p_h + (long)BB * NPTS * 64;

    static bool attr_done = false;
    if (!attr_done) {
        cudaFuncSetAttribute(topk_w, cudaFuncAttributeMaxDynamicSharedMemorySize,
                             8 * NPTS * 4);
        cudaFuncSetAttribute(edgeconv_p<3>, cudaFuncAttributeMaxDynamicSharedMemorySize,
                             ec_smem(3));
        cudaFuncSetAttribute(edgeconv_p<64>, cudaFuncAttributeMaxDynamicSharedMemorySize,
                             ec_smem(64));
        attr_done = true;
    }

    const long NN2 = (long)NPTS * NPTS;
    dim3 gSq(NPTS / 256, BB), bSq(256);
    dim3 gRow(NPTS, BB), bRow(256);
    dim3 gTopk(NPTS / 8, BB);
    dim3 gEc(NPTS / 16, BB);
    const int smemTopk = 8 * NPTS * 4;

    // ---- EdgeConv 1 (CIN=3): reads p_ft(3ch), dual-writes ft64_a ----
    sqnorm_k<<<gSq, bSq>>>(x, p_sq, 3, (long)3 * NPTS);
    gemm128<<<dim3(16, 16, BB), 256>>>(x, x, p_dot, NPTS, NPTS, 3,
                                       1, NPTS, (long)3 * NPTS,
                                       1, NPTS, (long)3 * NPTS,
                                       NPTS, NN2);
    transpose_k<<<dim3(NPTS / 256, 3, BB), 256>>>(x, (long)3 * NPTS, 3, p_ft);
    topk_w<<<gTopk, 256, smemTopk>>>(p_dot, p_sq, p_idx);
    edgeconv_p<3><<<gEc, 256, ec_smem(3)>>>(x, (long)3 * NPTS, p_ft, p_idx,
                                            ec1_w1, ec1_b1, ec1_w2, ec1_b2,
                                            p_xc, (long)192 * NPTS, ft64_a);

    // ---- EdgeConv 2 (CIN=64): reads ft64_a, dual-writes ft64_b ----
    sqnorm_k<<<gSq, bSq>>>(p_xc, p_sq, 64, (long)192 * NPTS);
    gemm128<<<dim3(16, 16, BB), 256>>>(p_xc, p_xc, p_dot, NPTS, NPTS, 64,
                                       1, NPTS, (long)192 * NPTS,
                                       1, NPTS, (long)192 * NPTS,
                                       NPTS, NN2);
    topk_w<<<gTopk, 256, smemTopk>>>(p_dot, p_sq, p_idx);
    edgeconv_p<64><<<gEc, 256, ec_smem(64)>>>(p_xc, (long)192 * NPTS, ft64_a, p_idx,
                                              ec2_w1, ec2_b1, ec2_w2, ec2_b2,
                                              p_xc + (long)64 * NPTS,
                                              (long)192 * NPTS, ft64_b);

    // ---- EdgeConv 3 (CIN=64): reads ft64_b ----
    sqnorm_k<<<gSq, bSq>>>(p_xc + (long)64 * NPTS, p_sq, 64, (long)192 * NPTS);
    gemm128<<<dim3(16, 16, BB), 256>>>(p_xc + (long)64 * NPTS, p_xc + (long)64 * NPTS,
                                       p_dot, NPTS, NPTS, 64,
                                       1, NPTS, (long)192 * NPTS,
                                       1, NPTS, (long)192 * NPTS,
                                       NPTS, NN2);
    topk_w<<<gTopk, 256, smemTopk>>>(p_dot, p_sq, p_idx);
    edgeconv_p<64><<<gEc, 256, ec_smem(64)>>>(p_xc + (long)64 * NPTS, (long)192 * NPTS,
                                              ft64_b, p_idx,
                                              ec3_w1, ec3_b1, ec3_w2, ec3_b2,
                                              p_xc + (long)128 * NPTS,
                                              (long)192 * NPTS, nullptr);

    // ---- emb: h = emb_w (1024x192) @ xc  (overwrites ft64 scratch in g_h) ----
    gemm_f16<<<dim3(16, 8, BB), 256>>>(emb_w, p_xc, p_h, 1024, NPTS, 192,
                                       192, 1, 0,
                                       1, NPTS, (long)192 * NPTS,
                                       NPTS, (long)1024 * NPTS, 0, nullptr, nullptr);

    // ---- q, k, v ----
    gemm_f16<<<dim3(16, 8, BB), 256>>>(q_w, p_h, p_q, 1024, NPTS, 1024,
                                       1024, 1, 0,
                                       1, NPTS, (long)1024 * NPTS,
                                       NPTS, (long)1024 * NPTS, 0, nullptr, nullptr);
    gemm_f16<<<dim3(16, 8, BB), 256>>>(k_w, p_h, p_k, 1024, NPTS, 1024,
                                       1024, 1, 0,
                                       1, NPTS, (long)1024 * NPTS,
                                       NPTS, (long)1024 * NPTS, 0, nullptr, nullptr);
    gemm_f16<<<dim3(16, 8, BB), 256>>>(v_w, p_h, p_v, 1024, NPTS, 1024,
                                       1024, 1, 0,
                                       1, NPTS, (long)1024 * NPTS,
                                       NPTS, (long)1024 * NPTS, 0, nullptr, nullptr);

    // ---- scores = q^T k ----
    gemm_f16<<<dim3(16, 16, BB), 256>>>(p_q, p_k, p_dot, NPTS, NPTS, 1024,
                                        1, NPTS, (long)1024 * NPTS,
                                        1, NPTS, (long)1024 * NPTS,
                                        NPTS, NN2, 0, nullptr, nullptr);
    softmax_s<<<gRow, bRow>>>(p_dot);

    // ---- h = bn(h + att @ v, att_bn1) ----
    gemm_f16<<<dim3(16, 8, BB), 256>>>(p_v, p_dot, p_h, 1024, NPTS, NPTS,
                                       NPTS, 1, (long)1024 * NPTS,
                                       NPTS, 1, NN2,
                                       NPTS, (long)1024 * NPTS, 3, attb1, p_h);

    // ---- ff1 = lrelu(ff_w1 @ h) ----
    gemm_f16<<<dim3(16, 4, BB), 256>>>(ff_w1, p_h, p_ff1, 512, NPTS, 1024,
                                       1024, 1, 0,
                                       1, NPTS, (long)1024 * NPTS,
                                       NPTS, (long)512 * NPTS, 1, nullptr, nullptr);

    // ---- h = bn(h + ff_w2 @ ff1, att_bn2) ----
    gemm_f16<<<dim3(16, 8, BB), 256>>>(ff_w2, p_ff1, p_h, 1024, NPTS, 512,
                                       512, 1, 0,
                                       1, NPTS, (long)512 * NPTS,
                                       NPTS, (long)1024 * NPTS, 3, attb2, p_h);

    // ---- out = lrelu(bn(cb_w @ h, cb_bn)) -> d_out ----
    gemm_f16<<<dim3(16, 8, BB), 256>>>(cb_w, p_h, (float*)d_out, 1024, NPTS, 1024,
                                       1024, 1, 0,
                                       1, NPTS, (long)1024 * NPTS,
                                       NPTS, (long)1024 * NPTS, 2, cb_bn, nullptr);
}

// round 16
// speedup vs baseline: 1.0172x; 1.0022x over previous
#include <cuda_runtime.h>
#include <cuda_bf16.h>
#include <cuda_fp16.h>
#include <cstdint>

#define BB   8
#define NPTS 2048
#define KNN  32
#define EPS  1e-5f

// ---------------------------------------------------------------------------
// Device scratch (static allocations only — no cudaMalloc allowed)
// ---------------------------------------------------------------------------
__device__ float g_dot[(long)BB * NPTS * NPTS];
__device__ float g_sq [(long)BB * NPTS];
__device__ int   g_idx[(long)BB * NPTS * KNN];
__device__ float g_xc [(long)BB * 192  * NPTS];
__device__ float g_ft [(long)BB * NPTS * 64];
__device__ float g_h  [(long)BB * 1024 * NPTS];
__device__ float g_q  [(long)BB * 1024 * NPTS];
__device__ float g_k  [(long)BB * 1024 * NPTS];
__device__ float g_v  [(long)BB * 1024 * NPTS];
__device__ float g_ff1[(long)BB * 512  * NPTS];

__device__ __forceinline__ uint32_t packh2(float x, float y) {
    __half2 h = __floats2half2_rn(x, y);
    return *(uint32_t*)&h;
}
__device__ __forceinline__ unsigned long long packkey(float v, int m) {
    uint32_t bu = __float_as_uint(v);
    bu ^= ((uint32_t)((int)bu >> 31)) | 0x80000000u;   // monotone sortable map
    return ((unsigned long long)bu << 32) | (uint32_t)m;
}

// ---------------------------------------------------------------------------
// FP16 tensor-core GEMM (m16n8k16, fp32 accumulate), double-buffered (R9 exact)
// epi: 0=none, 1=lrelu, 2=bn(i)+lrelu, 3=bn(acc + resid[i][j])
// ---------------------------------------------------------------------------
__global__ __launch_bounds__(256, 2)
void gemm_f16(const float* __restrict__ A, const float* __restrict__ B,
              float* __restrict__ C,
              int M, int N, int K,
              long laI, long laK, long sA,
              long lbJ, long lbK, long sB,
              long ldc, long sC,
              int epi, const float* __restrict__ bnp,
              const float* __restrict__ resid)
{
    __shared__ uint32_t As[2][8 * 136];
    __shared__ uint32_t Bs[2][8 * 136];

    const int tid  = threadIdx.x;
    const int lane = tid & 31;
    const int w    = tid >> 5;
    const int wm   = w >> 2;
    const int wn   = w & 3;
    const int i0   = blockIdx.y * 128;
    const int j0   = blockIdx.x * 128;

    const float* Ab = A + (long)blockIdx.z * sA;
    const float* Bb = B + (long)blockIdx.z * sB;
    const bool aKf = (laK == 1);
    const bool bKf = (lbK == 1);

    int aiv[4], akp[4], bjv[4], bkp[4];
#pragma unroll
    for (int u = 0; u < 4; u++) {
        int q = u * 256 + tid;
        if (aKf) { akp[u] = q & 7; aiv[u] = q >> 3; }
        else     { akp[u] = q >> 7; aiv[u] = q & 127; }
        if (bKf) { bkp[u] = q & 7; bjv[u] = q >> 3; }
        else     { bkp[u] = q >> 7; bjv[u] = q & 127; }
    }

    float acc[4][4][4];
#pragma unroll
    for (int mi = 0; mi < 4; mi++)
#pragma unroll
        for (int ni = 0; ni < 4; ni++)
#pragma unroll
            for (int r = 0; r < 4; r++) acc[mi][ni][r] = 0.f;

    const int qrow = lane >> 2;
    const int qcol = lane & 3;

    float2 ra[4], rb[4];
    auto stage_load = [&](int kt) {
        const long kb = (long)kt * 16;
#pragma unroll
        for (int u = 0; u < 4; u++) {
            if (aKf) {
                ra[u] = *(const float2*)(Ab + (long)(i0 + aiv[u]) * laI + kb + 2 * akp[u]);
            } else {
                const float* p = Ab + (kb + 2 * akp[u]) * laK + i0 + aiv[u];
                ra[u].x = p[0]; ra[u].y = p[laK];
            }
            if (bKf) {
                rb[u] = *(const float2*)(Bb + (long)(j0 + bjv[u]) * lbJ + kb + 2 * bkp[u]);
            } else {
                const float* p = Bb + (kb + 2 * bkp[u]) * lbK + j0 + bjv[u];
                rb[u].x = p[0]; rb[u].y = p[lbK];
            }
        }
    };
    auto stage_store = [&](int buf) {
#pragma unroll
        for (int u = 0; u < 4; u++) {
            As[buf][akp[u] * 136 + aiv[u]] = packh2(ra[u].x, ra[u].y);
            Bs[buf][bkp[u] * 136 + bjv[u]] = packh2(rb[u].x, rb[u].y);
        }
    };

    stage_load(0);
    stage_store(0);
    __syncthreads();

    const int nkt = K / 16;
    for (int kt = 0; kt < nkt; kt++) {
        const int cur = kt & 1;
        const bool more = (kt + 1 < nkt);
        if (more) stage_load(kt + 1);

        const uint32_t* Ac = As[cur];
        const uint32_t* Bc = Bs[cur];
        uint32_t af[4][4], bf[4][2];
#pragma unroll
        for (int mi = 0; mi < 4; mi++) {
            int m0 = wm * 64 + mi * 16 + qrow;
            af[mi][0] = Ac[qcol * 136 + m0];
            af[mi][1] = Ac[qcol * 136 + m0 + 8];
            af[mi][2] = Ac[(qcol + 4) * 136 + m0];
            af[mi][3] = Ac[(qcol + 4) * 136 + m0 + 8];
        }
#pragma unroll
        for (int ni = 0; ni < 4; ni++) {
            int n0 = wn * 32 + ni * 8 + qrow;
            bf[ni][0] = Bc[qcol * 136 + n0];
            bf[ni][1] = Bc[(qcol + 4) * 136 + n0];
        }
#pragma unroll
        for (int mi = 0; mi < 4; mi++)
#pragma unroll
            for (int ni = 0; ni < 4; ni++) {
                asm volatile(
                    "mma.sync.aligned.m16n8k16.row.col.f32.f16.f16.f32 "
                    "{%0,%1,%2,%3}, {%4,%5,%6,%7}, {%8,%9}, {%0,%1,%2,%3};"
                    : "+f"(acc[mi][ni][0]), "+f"(acc[mi][ni][1]),
                      "+f"(acc[mi][ni][2]), "+f"(acc[mi][ni][3])
                    : "r"(af[mi][0]), "r"(af[mi][1]), "r"(af[mi][2]), "r"(af[mi][3]),
                      "r"(bf[ni][0]), "r"(bf[ni][1]));
            }

        if (more) {
            stage_store(cur ^ 1);
            __syncthreads();
        }
    }

    float* Cb = C + (long)blockIdx.z * sC;
    const float* Rb = resid ? (resid + (long)blockIdx.z * sC) : nullptr;
#pragma unroll
    for (int mi = 0; mi < 4; mi++) {
        int r0 = i0 + wm * 64 + mi * 16 + qrow;
        int r1 = r0 + 8;
        float s0 = 1.f, t0 = 0.f, s1 = 1.f, t1 = 0.f;
        if (epi >= 2) {
            float g = bnp[r0], bb = bnp[M + r0], m = bnp[2 * M + r0], vv = bnp[3 * M + r0];
            s0 = g * rsqrtf(vv + EPS); t0 = bb - m * s0;
            g = bnp[r1]; bb = bnp[M + r1]; m = bnp[2 * M + r1]; vv = bnp[3 * M + r1];
            s1 = g * rsqrtf(vv + EPS); t1 = bb - m * s1;
        }
#pragma unroll
        for (int ni = 0; ni < 4; ni++) {
            int cc = j0 + wn * 32 + ni * 8 + 2 * qcol;
            float y0 = acc[mi][ni][0], y1 = acc[mi][ni][1];
            float y2 = acc[mi][ni][2], y3 = acc[mi][ni][3];
            if (epi == 1) {
                y0 = (y0 >= 0.f) ? y0 : 0.2f * y0;
                y1 = (y1 >= 0.f) ? y1 : 0.2f * y1;
                y2 = (y2 >= 0.f) ? y2 : 0.2f * y2;
                y3 = (y3 >= 0.f) ? y3 : 0.2f * y3;
            } else if (epi == 2) {
                y0 = y0 * s0 + t0; y0 = (y0 >= 0.f) ? y0 : 0.2f * y0;
                y1 = y1 * s0 + t0; y1 = (y1 >= 0.f) ? y1 : 0.2f * y1;
                y2 = y2 * s1 + t1; y2 = (y2 >= 0.f) ? y2 : 0.2f * y2;
                y3 = y3 * s1 + t1; y3 = (y3 >= 0.f) ? y3 : 0.2f * y3;
            } else if (epi == 3) {
                float2 z0 = *(const float2*)(Rb + (long)r0 * ldc + cc);
                float2 z1 = *(const float2*)(Rb + (long)r1 * ldc + cc);
                y0 = (y0 + z0.x) * s0 + t0;
                y1 = (y1 + z0.y) * s0 + t0;
                y2 = (y2 + z1.x) * s1 + t1;
                y3 = (y3 + z1.y) * s1 + t1;
            }
            *(float2*)(Cb + (long)r0 * ldc + cc) = make_float2(y0, y1);
            *(float2*)(Cb + (long)r1 * ldc + cc) = make_float2(y2, y3);
        }
    }
}

// ---------------------------------------------------------------------------
// fp32 SGEMM (kNN dot products — selection is tie-sensitive, stays fp32)
// ---------------------------------------------------------------------------
__global__ void gemm128(const float* __restrict__ A, const float* __restrict__ B,
                        float* __restrict__ C,
                        int M, int N, int K,
                        long laI, long laK, long sA,
                        long lbJ, long lbK, long sB,
                        long ldc, long sC)
{
    __shared__ float4 As4[8 * 33];
    __shared__ float4 Bs4[8 * 33];
    float* As = (float*)As4;
    float* Bs = (float*)Bs4;

    const int tid = threadIdx.x;
    const int tx  = tid & 15;
    const int ty  = tid >> 4;
    const int i0  = blockIdx.y * 128;
    const int j0  = blockIdx.x * 128;

    const float* Ab = A + (long)blockIdx.z * sA;
    const float* Bb = B + (long)blockIdx.z * sB;

    const bool aKfast = (laK == 1);
    const bool bKfast = (lbK == 1);

    float acc[8][8];
#pragma unroll
    for (int r = 0; r < 8; r++)
#pragma unroll
        for (int c = 0; c < 8; c++) acc[r][c] = 0.f;

    for (int k0 = 0; k0 < K; k0 += 8) {
#pragma unroll
        for (int u = 0; u < 4; u++) {
            int l = tid + u * 256;
            int i, k;
            if (aKfast) { i = l >> 3; k = l & 7; }
            else        { i = l & 127; k = l >> 7; }
            int kg = k0 + k;
            float v = 0.f;
            if (kg < K) v = Ab[(long)(i0 + i) * laI + (long)kg * laK];
            As[k * 132 + i] = v;
        }
#pragma unroll
        for (int u = 0; u < 4; u++) {
            int l = tid + u * 256;
            int j, k;
            if (bKfast) { j = l >> 3; k = l & 7; }
            else        { j = l & 127; k = l >> 7; }
            int kg = k0 + k;
            float v = 0.f;
            if (kg < K) v = Bb[(long)(j0 + j) * lbJ + (long)kg * lbK];
            Bs[k * 132 + j] = v;
        }
        __syncthreads();

#pragma unroll
        for (int kk = 0; kk < 8; kk++) {
            const float4* Ar = (const float4*)(As + kk * 132);
            const float4* Br = (const float4*)(Bs + kk * 132);
            float4 a0 = Ar[ty * 2], a1 = Ar[ty * 2 + 1];
            float4 b0 = Br[tx * 2], b1 = Br[tx * 2 + 1];
            float av[8] = {a0.x, a0.y, a0.z, a0.w, a1.x, a1.y, a1.z, a1.w};
            float bv[8] = {b0.x, b0.y, b0.z, b0.w, b1.x, b1.y, b1.z, b1.w};
#pragma unroll
            for (int r = 0; r < 8; r++)
#pragma unroll
                for (int c = 0; c < 8; c++)
                    acc[r][c] += av[r] * bv[c];
        }
        __syncthreads();
    }

    float* Cb = C + (long)blockIdx.z * sC;
#pragma unroll
    for (int r = 0; r < 8; r++) {
        int ig = i0 + ty * 8 + r;
        float4* dst = (float4*)(Cb + (long)ig * ldc + (j0 + tx * 8));
        dst[0] = make_float4(acc[r][0], acc[r][1], acc[r][2], acc[r][3]);
        dst[1] = make_float4(acc[r][4], acc[r][5], acc[r][6], acc[r][7]);
    }
}

// ---------------------------------------------------------------------------
// Squared norm per point
// ---------------------------------------------------------------------------
__global__ void sqnorm_k(const float* __restrict__ f, float* __restrict__ sq,
                         int C, long bstride)
{
    int n = blockIdx.x * blockDim.x + threadIdx.x;
    int b = blockIdx.y;
    if (n >= NPTS) return;
    const float* fb = f + (long)b * bstride;
    float s = 0.f;
    for (int c = 0; c < C; c++) {
        float v = fb[(long)c * NPTS + n];
        s += v * v;
    }
    sq[(long)b * NPTS + n] = s;
}

// ---------------------------------------------------------------------------
// Feature transpose: ft[b][n][c] = f[b][c][n]  (only for 3-ch layer-1 input)
// ---------------------------------------------------------------------------
__global__ void transpose_k(const float* __restrict__ f, long fBS, int C,
                            float* __restrict__ ft)
{
    int n = blockIdx.x * 256 + threadIdx.x;
    int c = blockIdx.y, b = blockIdx.z;
    ft[((long)b * NPTS + n) * C + c] = f[(long)b * fBS + (long)c * NPTS + n];
}

// ---------------------------------------------------------------------------
// Top-K (32 smallest), warp-per-row, smem key cache.
// Key-build front-batches ALL 16 float4 dot loads (MLP=16) before consuming —
// the kernel is DRAM-bound on this read. Selection identical to R12.
// ---------------------------------------------------------------------------
__global__ __launch_bounds__(256)
void topk_w(const float* __restrict__ dot, const float* __restrict__ sq,
            int* __restrict__ idx)
{
    extern __shared__ float skey[];
    const int lane = threadIdx.x & 31;
    const int wid  = threadIdx.x >> 5;
    const int n = blockIdx.x * 8 + wid;
    const int b = blockIdx.y;
    float* key = skey + wid * NPTS;
    const float* drow = dot + ((long)b * NPTS + n) * NPTS;
    const float* sqb  = sq + (long)b * NPTS;

    unsigned long long cmin[8];
#pragma unroll
    for (int ch = 0; ch < 8; ch++) cmin[ch] = ~0ull;

    // front-batched loads: 16 float4 in flight per warp
    float4 dv[16];
#pragma unroll
    for (int t16 = 0; t16 < 16; t16++)
        dv[t16] = *(const float4*)(drow + t16 * 128 + lane * 4);

#pragma unroll
    for (int t16 = 0; t16 < 16; t16++) {
        int m0 = t16 * 128 + lane * 4;
        float4 sv = *(const float4*)(sqb + m0);
        float v0 = sv.x - 2.f * dv[t16].x;
        float v1 = sv.y - 2.f * dv[t16].y;
        float v2 = sv.z - 2.f * dv[t16].z;
        float v3 = sv.w - 2.f * dv[t16].w;
        *(float4*)(key + m0) = make_float4(v0, v1, v2, v3);
        int ch = t16 >> 1;
        unsigned long long k0 = packkey(v0, m0);
        unsigned long long k1 = packkey(v1, m0 + 1);
        unsigned long long k2 = packkey(v2, m0 + 2);
        unsigned long long k3 = packkey(v3, m0 + 3);
        if (k1 < k0) k0 = k1;
        if (k3 < k2) k2 = k3;
        if (k2 < k0) k0 = k2;
        if (k0 < cmin[ch]) cmin[ch] = k0;
    }
    unsigned long long laneMin = cmin[0];
#pragma unroll
    for (int ch = 1; ch < 8; ch++) if (cmin[ch] < laneMin) laneMin = cmin[ch];

    int* orow = idx + ((long)b * NPTS + n) * KNN;
    for (int it = 0; it < KNN; it++) {
        unsigned long long r = laneMin;
#pragma unroll
        for (int off = 16; off; off >>= 1) {
            unsigned long long o = __shfl_xor_sync(0xffffffffu, r, off);
            if (o < r) r = o;
        }
        int ri = (int)(uint32_t)r;
        if (lane == 0) orow[it] = ri;
        if (lane == ((ri >> 2) & 31)) {
            key[ri] = 3.4e38f;
            int ch = ri >> 8;
            unsigned long long nm = ~0ull;
#pragma unroll
            for (int t2 = 0; t2 < 2; t2++) {
                int m0 = (ch * 2 + t2) * 128 + lane * 4;
                float4 kv = *(const float4*)(key + m0);
                unsigned long long k0 = packkey(kv.x, m0);
                unsigned long long k1 = packkey(kv.y, m0 + 1);
                unsigned long long k2 = packkey(kv.z, m0 + 2);
                unsigned long long k3 = packkey(kv.w, m0 + 3);
                if (k1 < k0) k0 = k1;
                if (k3 < k2) k2 = k3;
                if (k2 < k0) k0 = k2;
                if (k0 < nm) nm = k0;
            }
            cmin[ch] = nm;
            laneMin = cmin[0];
#pragma unroll
            for (int c2 = 1; c2 < 8; c2++) if (cmin[c2] < laneMin) laneMin = cmin[c2];
        }
        __syncwarp();
    }
}

// ---------------------------------------------------------------------------
// Fused EdgeConv, 16 points/block + optional dual-write into DISJOINT
// point-major ft buffer (R15, passing)
// ---------------------------------------------------------------------------
template<int CIN>
__global__ __launch_bounds__(256)
void edgeconv_p(const float* __restrict__ f, long fBS,
                const float* __restrict__ ft,
                const int* __restrict__ idxg,
                const float* __restrict__ w1, const float* __restrict__ bn1,
                const float* __restrict__ w2, const float* __restrict__ bn2,
                float* __restrict__ out, long oBS,
                float* __restrict__ ftOut)
{
    constexpr int CP = CIN + 1;
    extern __shared__ float sm[];
    float* W1A  = sm;
    float* W1D  = W1A + CIN * 64;
    float* W2S  = W1D + CIN * 64;
    float* BN   = W2S + 4096;
    float* CTR  = BN + 256;
    float* US   = CTR + CIN * 16;
    int*   IDS  = (int*)(US + 1024);
    float* BUFA = (float*)(IDS + 512);
    float* BUFH = BUFA + 2 * 32 * CP;

    const int tid = threadIdx.x;
    const int n0 = blockIdx.x * 16;
    const int b  = blockIdx.y;
    const float* fb  = f + (long)b * fBS;
    const float* ftb = ft + (long)b * NPTS * CIN;

    for (int l = tid; l < CIN * 64; l += 256) {
        int o = l & 63, c = l >> 6;
        float a = w1[o * (2 * CIN) + c];
        W1A[c * 64 + o] = a;
        W1D[c * 64 + o] = w1[o * (2 * CIN) + CIN + c] - a;
    }
    for (int l = tid; l < 4096; l += 256) {
        int o = l & 63, c = l >> 6;
        W2S[c * 64 + o] = w2[o * 64 + c];
    }
    if (tid < 64) {
        float g = bn1[tid], bb = bn1[64 + tid], m = bn1[128 + tid], vv = bn1[192 + tid];
        float s = g * rsqrtf(vv + EPS);
        BN[tid] = s; BN[64 + tid] = bb - m * s;
        g = bn2[tid]; bb = bn2[64 + tid]; m = bn2[128 + tid]; vv = bn2[192 + tid];
        s = g * rsqrtf(vv + EPS);
        BN[128 + tid] = s; BN[192 + tid] = bb - m * s;
    }
    for (int l = tid; l < CIN * 16; l += 256) {
        int c = l >> 4, p = l & 15;
        CTR[c * 16 + p] = fb[(long)c * NPTS + n0 + p];
    }
    for (int l = tid; l < 512; l += 256)
        IDS[l] = idxg[((long)b * NPTS + n0 + (l >> 5)) * KNN + (l & 31)];
    __syncthreads();

#pragma unroll
    for (int r = 0; r < 4; r++) {
        int q = tid + 256 * r;
        int p = q >> 6, o = q & 63;
        float a = 0.f;
        for (int c = 0; c < CIN; c++)
            a += W1D[c * 64 + o] * CTR[c * 16 + p];
        US[p * 64 + o] = a;
    }

    auto gather = [&](int p, int buf) {
        float* dst = BUFA + buf * 32 * CP;
        if (CIN == 64) {
            for (int l = tid; l < 2048; l += 256) {
                int k = l >> 6, c = l & 63;
                dst[k * CP + c] = ftb[(long)IDS[p * 32 + k] * 64 + c];
            }
        } else {
            for (int l = tid; l < 32 * CIN; l += 256) {
                int k = l / CIN, c = l % CIN;
                dst[k * CP + c] = ftb[(long)IDS[p * 32 + k] * CIN + c];
            }
        }
    };
    gather(0, 0);
    __syncthreads();

    const int k  = tid & 31;
    const int og = tid >> 5;
    float* ob = out + (long)b * oBS;
    float* fo = ftOut ? (ftOut + (long)b * NPTS * 64) : nullptr;

    for (int p = 0; p < 16; p++) {
        const int cur = p & 1;
        const float* A = BUFA + cur * 32 * CP + k * CP;

        float acc[8];
#pragma unroll
        for (int j = 0; j < 8; j++) acc[j] = 0.f;
        for (int c = 0; c < CIN; c++) {
            float nv = A[c];
#pragma unroll
            for (int j = 0; j < 8; j++)
                acc[j] += W1A[c * 64 + og * 8 + j] * nv;
        }
#pragma unroll
        for (int j = 0; j < 8; j++) {
            int o = og * 8 + j;
            float y = (acc[j] + US[p * 64 + o]) * BN[o] + BN[64 + o];
            BUFH[k * 65 + o] = (y >= 0.f) ? y : 0.2f * y;
        }
        if (p + 1 < 16) gather(p + 1, cur ^ 1);
        __syncthreads();

        float acc2[8];
#pragma unroll
        for (int j = 0; j < 8; j++) acc2[j] = 0.f;
        for (int c = 0; c < 64; c++) {
            float hv = BUFH[k * 65 + c];
#pragma unroll
            for (int j = 0; j < 8; j++)
                acc2[j] += W2S[c * 64 + og * 8 + j] * hv;
        }
        float yout[8];
#pragma unroll
        for (int j = 0; j < 8; j++) {
            int o = og * 8 + j;
            float y = acc2[j] * BN[128 + o] + BN[192 + o];
            y = (y >= 0.f) ? y : 0.2f * y;
#pragma unroll
            for (int off = 16; off; off >>= 1)
                y = fmaxf(y, __shfl_xor_sync(0xffffffffu, y, off));
            yout[j] = y;
            if (k == 0) ob[(long)o * NPTS + n0 + p] = y;
        }
        if (fo && k == 0) {
            float4* dst = (float4*)(fo + (long)(n0 + p) * 64 + og * 8);
            dst[0] = make_float4(yout[0], yout[1], yout[2], yout[3]);
            dst[1] = make_float4(yout[4], yout[5], yout[6], yout[7]);
        }
        __syncthreads();
    }
}

// ---------------------------------------------------------------------------
// Row softmax, single read + single write (R7, passing)
// ---------------------------------------------------------------------------
__global__ __launch_bounds__(256)
void softmax_s(float* __restrict__ S)
{
    __shared__ float red[8];
    const int tid = threadIdx.x, lane = tid & 31, wid = tid >> 5;
    float* row = S + ((long)blockIdx.y * NPTS + blockIdx.x) * NPTS;
    const float scale = 0.03125f;

    float4 v0 = *(float4*)(row + tid * 8);
    float4 v1 = *(float4*)(row + tid * 8 + 4);
    float mx = fmaxf(fmaxf(fmaxf(v0.x, v0.y), fmaxf(v0.z, v0.w)),
                     fmaxf(fmaxf(v1.x, v1.y), fmaxf(v1.z, v1.w)));
#pragma unroll
    for (int off = 16; off; off >>= 1)
        mx = fmaxf(mx, __shfl_xor_sync(0xffffffffu, mx, off));
    if (lane == 0) red[wid] = mx;
    __syncthreads();
    mx = fmaxf(fmaxf(fmaxf(red[0], red[1]), fmaxf(red[2], red[3])),
               fmaxf(fmaxf(red[4], red[5]), fmaxf(red[6], red[7])));
    __syncthreads();

    v0.x = __expf((v0.x - mx) * scale); v0.y = __expf((v0.y - mx) * scale);
    v0.z = __expf((v0.z - mx) * scale); v0.w = __expf((v0.w - mx) * scale);
    v1.x = __expf((v1.x - mx) * scale); v1.y = __expf((v1.y - mx) * scale);
    v1.z = __expf((v1.z - mx) * scale); v1.w = __expf((v1.w - mx) * scale);
    float sum = v0.x + v0.y + v0.z + v0.w + v1.x + v1.y + v1.z + v1.w;
#pragma unroll
    for (int off = 16; off; off >>= 1)
        sum += __shfl_xor_sync(0xffffffffu, sum, off);
    if (lane == 0) red[wid] = sum;
    __syncthreads();
    sum = red[0] + red[1] + red[2] + red[3] + red[4] + red[5] + red[6] + red[7];
    float inv = 1.f / sum;

    v0.x *= inv; v0.y *= inv; v0.z *= inv; v0.w *= inv;
    v1.x *= inv; v1.y *= inv; v1.z *= inv; v1.w *= inv;
    *(float4*)(row + tid * 8)     = v0;
    *(float4*)(row + tid * 8 + 4) = v1;
}

// ---------------------------------------------------------------------------
// Launch
// ---------------------------------------------------------------------------
static inline int ec_smem(int cin) {
    return (2 * cin * 64 + 4096 + 256 + cin * 16 + 1024) * 4
         + 512 * 4
         + (2 * 32 * (cin + 1) + 32 * 65) * 4;
}

extern "C" void kernel_launch(void* const* d_in, const int* in_sizes, int n_in,
                              void* d_out, int out_size)
{
    const float* x      = (const float*)d_in[0];
    const float* ec1_w1 = (const float*)d_in[1];
    const float* ec1_b1 = (const float*)d_in[2];
    const float* ec1_w2 = (const float*)d_in[3];
    const float* ec1_b2 = (const float*)d_in[4];
    const float* ec2_w1 = (const float*)d_in[5];
    const float* ec2_b1 = (const float*)d_in[6];
    const float* ec2_w2 = (const float*)d_in[7];
    const float* ec2_b2 = (const float*)d_in[8];
    const float* ec3_w1 = (const float*)d_in[9];
    const float* ec3_b1 = (const float*)d_in[10];
    const float* ec3_w2 = (const float*)d_in[11];
    const float* ec3_b2 = (const float*)d_in[12];
    const float* emb_w  = (const float*)d_in[13];
    const float* q_w    = (const float*)d_in[14];
    const float* k_w    = (const float*)d_in[15];
    const float* v_w    = (const float*)d_in[16];
    const float* attb1  = (const float*)d_in[17];
    const float* ff_w1  = (const float*)d_in[18];
    const float* ff_w2  = (const float*)d_in[19];
    const float* attb2  = (const float*)d_in[20];
    const float* cb_w   = (const float*)d_in[21];
    const float* cb_bn  = (const float*)d_in[22];

    float *p_dot, *p_sq, *p_xc, *p_ft, *p_h, *p_q, *p_k, *p_v, *p_ff1;
    int* p_idx;
    cudaGetSymbolAddress((void**)&p_dot, g_dot);
    cudaGetSymbolAddress((void**)&p_sq,  g_sq);
    cudaGetSymbolAddress((void**)&p_idx, g_idx);
    cudaGetSymbolAddress((void**)&p_xc,  g_xc);
    cudaGetSymbolAddress((void**)&p_ft,  g_ft);
    cudaGetSymbolAddress((void**)&p_h,   g_h);
    cudaGetSymbolAddress((void**)&p_q,   g_q);
    cudaGetSymbolAddress((void**)&p_k,   g_k);
    cudaGetSymbolAddress((void**)&p_v,   g_v);
    cudaGetSymbolAddress((void**)&p_ff1, g_ff1);

    // disjoint point-major feature slabs carved from g_h (emb overwrites later)
    float* ft64_a = p_h;
    float* ft64_b = p_h + (long)BB * NPTS * 64;

    static bool attr_done = false;
    if (!attr_done) {
        cudaFuncSetAttribute(topk_w, cudaFuncAttributeMaxDynamicSharedMemorySize,
                             8 * NPTS * 4);
        cudaFuncSetAttribute(edgeconv_p<3>, cudaFuncAttributeMaxDynamicSharedMemorySize,
                             ec_smem(3));
        cudaFuncSetAttribute(edgeconv_p<64>, cudaFuncAttributeMaxDynamicSharedMemorySize,
                             ec_smem(64));
        attr_done = true;
    }

    const long NN2 = (long)NPTS * NPTS;
    dim3 gSq(NPTS / 256, BB), bSq(256);
    dim3 gRow(NPTS, BB), bRow(256);
    dim3 gTopk(NPTS / 8, BB);
    dim3 gEc(NPTS / 16, BB);
    const int smemTopk = 8 * NPTS * 4;

    // ---- EdgeConv 1 (CIN=3): reads p_ft(3ch), dual-writes ft64_a ----
    sqnorm_k<<<gSq, bSq>>>(x, p_sq, 3, (long)3 * NPTS);
    gemm128<<<dim3(16, 16, BB), 256>>>(x, x, p_dot, NPTS, NPTS, 3,
                                       1, NPTS, (long)3 * NPTS,
                                       1, NPTS, (long)3 * NPTS,
                                       NPTS, NN2);
    transpose_k<<<dim3(NPTS / 256, 3, BB), 256>>>(x, (long)3 * NPTS, 3, p_ft);
    topk_w<<<gTopk, 256, smemTopk>>>(p_dot, p_sq, p_idx);
    edgeconv_p<3><<<gEc, 256, ec_smem(3)>>>(x, (long)3 * NPTS, p_ft, p_idx,
                                            ec1_w1, ec1_b1, ec1_w2, ec1_b2,
                                            p_xc, (long)192 * NPTS, ft64_a);

    // ---- EdgeConv 2 (CIN=64): reads ft64_a, dual-writes ft64_b ----
    sqnorm_k<<<gSq, bSq>>>(p_xc, p_sq, 64, (long)192 * NPTS);
    gemm128<<<dim3(16, 16, BB), 256>>>(p_xc, p_xc, p_dot, NPTS, NPTS, 64,
                                       1, NPTS, (long)192 * NPTS,
                                       1, NPTS, (long)192 * NPTS,
                                       NPTS, NN2);
    topk_w<<<gTopk, 256, smemTopk>>>(p_dot, p_sq, p_idx);
    edgeconv_p<64><<<gEc, 256, ec_smem(64)>>>(p_xc, (long)192 * NPTS, ft64_a, p_idx,
                                              ec2_w1, ec2_b1, ec2_w2, ec2_b2,
                                              p_xc + (long)64 * NPTS,
                                              (long)192 * NPTS, ft64_b);

    // ---- EdgeConv 3 (CIN=64): reads ft64_b ----
    sqnorm_k<<<gSq, bSq>>>(p_xc + (long)64 * NPTS, p_sq, 64, (long)192 * NPTS);
    gemm128<<<dim3(16, 16, BB), 256>>>(p_xc + (long)64 * NPTS, p_xc + (long)64 * NPTS,
                                       p_dot, NPTS, NPTS, 64,
                                       1, NPTS, (long)192 * NPTS,
                                       1, NPTS, (long)192 * NPTS,
                                       NPTS, NN2);
    topk_w<<<gTopk, 256, smemTopk>>>(p_dot, p_sq, p_idx);
    edgeconv_p<64><<<gEc, 256, ec_smem(64)>>>(p_xc + (long)64 * NPTS, (long)192 * NPTS,
                                              ft64_b, p_idx,
                                              ec3_w1, ec3_b1, ec3_w2, ec3_b2,
                                              p_xc + (long)128 * NPTS,
                                              (long)192 * NPTS, nullptr);

    // ---- emb: h = emb_w (1024x192) @ xc  (overwrites ft64 scratch in g_h) ----
    gemm_f16<<<dim3(16, 8, BB), 256>>>(emb_w, p_xc, p_h, 1024, NPTS, 192,
                                       192, 1, 0,
                                       1, NPTS, (long)192 * NPTS,
                                       NPTS, (long)1024 * NPTS, 0, nullptr, nullptr);

    // ---- q, k, v ----
    gemm_f16<<<dim3(16, 8, BB), 256>>>(q_w, p_h, p_q, 1024, NPTS, 1024,
                                       1024, 1, 0,
                                       1, NPTS, (long)1024 * NPTS,
                                       NPTS, (long)1024 * NPTS, 0, nullptr, nullptr);
    gemm_f16<<<dim3(16, 8, BB), 256>>>(k_w, p_h, p_k, 1024, NPTS, 1024,
                                       1024, 1, 0,
                                       1, NPTS, (long)1024 * NPTS,
                                       NPTS, (long)1024 * NPTS, 0, nullptr, nullptr);
    gemm_f16<<<dim3(16, 8, BB), 256>>>(v_w, p_h, p_v, 1024, NPTS, 1024,
                                       1024, 1, 0,
                                       1, NPTS, (long)1024 * NPTS,
                                       NPTS, (long)1024 * NPTS, 0, nullptr, nullptr);

    // ---- scores = q^T k ----
    gemm_f16<<<dim3(16, 16, BB), 256>>>(p_q, p_k, p_dot, NPTS, NPTS, 1024,
                                        1, NPTS, (long)1024 * NPTS,
                                        1, NPTS, (long)1024 * NPTS,
                                        NPTS, NN2, 0, nullptr, nullptr);
    softmax_s<<<gRow, bRow>>>(p_dot);

    // ---- h = bn(h + att @ v, att_bn1) ----
    gemm_f16<<<dim3(16, 8, BB), 256>>>(p_v, p_dot, p_h, 1024, NPTS, NPTS,
                                       NPTS, 1, (long)1024 * NPTS,
                                       NPTS, 1, NN2,
                                       NPTS, (long)1024 * NPTS, 3, attb1, p_h);

    // ---- ff1 = lrelu(ff_w1 @ h) ----
    gemm_f16<<<dim3(16, 4, BB), 256>>>(ff_w1, p_h, p_ff1, 512, NPTS, 1024,
                                       1024, 1, 0,
                                       1, NPTS, (long)1024 * NPTS,
                                       NPTS, (long)512 * NPTS, 1, nullptr, nullptr);

    // ---- h = bn(h + ff_w2 @ ff1, att_bn2) ----
    gemm_f16<<<dim3(16, 8, BB), 256>>>(ff_w2, p_ff1, p_h, 1024, NPTS, 512,
                                       512, 1, 0,
                                       1, NPTS, (long)512 * NPTS,
                                       NPTS, (long)1024 * NPTS, 3, attb2, p_h);

    // ---- out = lrelu(bn(cb_w @ h, cb_bn)) -> d_out ----
    gemm_f16<<<dim3(16, 8, BB), 256>>>(cb_w, p_h, (float*)d_out, 1024, NPTS, 1024,
                                       1024, 1, 0,
                                       1, NPTS, (long)1024 * NPTS,
                                       NPTS, (long)1024 * NPTS, 2, cb_bn, nullptr);
}

// round 17
// speedup vs baseline: 1.0794x; 1.0611x over previous
#include <cuda_runtime.h>
#include <cuda_bf16.h>
#include <cuda_fp16.h>
#include <cstdint>

#define BB   8
#define NPTS 2048
#define KNN  32
#define EPS  1e-5f

// ---------------------------------------------------------------------------
// Device scratch (static allocations only — no cudaMalloc allowed)
// ---------------------------------------------------------------------------
__device__ float g_dot[(long)BB * NPTS * NPTS];
__device__ float g_sq [(long)BB * NPTS];
__device__ int   g_idx[(long)BB * NPTS * KNN];
__device__ float g_xc [(long)BB * 192  * NPTS];
__device__ float g_ft [(long)BB * NPTS * 64];
__device__ float g_h  [(long)BB * 1024 * NPTS];
__device__ float g_q  [(long)BB * 1024 * NPTS];
__device__ float g_k  [(long)BB * 1024 * NPTS];
__device__ float g_v  [(long)BB * 1024 * NPTS];
__device__ float g_ff1[(long)BB * 512  * NPTS];

__device__ __forceinline__ uint32_t packh2(float x, float y) {
    __half2 h = __floats2half2_rn(x, y);
    return *(uint32_t*)&h;
}
__device__ __forceinline__ unsigned long long packkey(float v, int m) {
    uint32_t bu = __float_as_uint(v);
    bu ^= ((uint32_t)((int)bu >> 31)) | 0x80000000u;   // monotone sortable map
    return ((unsigned long long)bu << 32) | (uint32_t)m;
}

// ---------------------------------------------------------------------------
// FP16 tensor-core GEMM (m16n8k16, fp32 accumulate), double-buffered (R9 exact)
// epi: 0=none, 1=lrelu, 2=bn(i)+lrelu, 3=bn(acc + resid[i][j])
// ---------------------------------------------------------------------------
__global__ __launch_bounds__(256, 2)
void gemm_f16(const float* __restrict__ A, const float* __restrict__ B,
              float* __restrict__ C,
              int M, int N, int K,
              long laI, long laK, long sA,
              long lbJ, long lbK, long sB,
              long ldc, long sC,
              int epi, const float* __restrict__ bnp,
              const float* __restrict__ resid)
{
    __shared__ uint32_t As[2][8 * 136];
    __shared__ uint32_t Bs[2][8 * 136];

    const int tid  = threadIdx.x;
    const int lane = tid & 31;
    const int w    = tid >> 5;
    const int wm   = w >> 2;
    const int wn   = w & 3;
    const int i0   = blockIdx.y * 128;
    const int j0   = blockIdx.x * 128;

    const float* Ab = A + (long)blockIdx.z * sA;
    const float* Bb = B + (long)blockIdx.z * sB;
    const bool aKf = (laK == 1);
    const bool bKf = (lbK == 1);

    int aiv[4], akp[4], bjv[4], bkp[4];
#pragma unroll
    for (int u = 0; u < 4; u++) {
        int q = u * 256 + tid;
        if (aKf) { akp[u] = q & 7; aiv[u] = q >> 3; }
        else     { akp[u] = q >> 7; aiv[u] = q & 127; }
        if (bKf) { bkp[u] = q & 7; bjv[u] = q >> 3; }
        else     { bkp[u] = q >> 7; bjv[u] = q & 127; }
    }

    float acc[4][4][4];
#pragma unroll
    for (int mi = 0; mi < 4; mi++)
#pragma unroll
        for (int ni = 0; ni < 4; ni++)
#pragma unroll
            for (int r = 0; r < 4; r++) acc[mi][ni][r] = 0.f;

    const int qrow = lane >> 2;
    const int qcol = lane & 3;

    float2 ra[4], rb[4];
    auto stage_load = [&](int kt) {
        const long kb = (long)kt * 16;
#pragma unroll
        for (int u = 0; u < 4; u++) {
            if (aKf) {
                ra[u] = *(const float2*)(Ab + (long)(i0 + aiv[u]) * laI + kb + 2 * akp[u]);
            } else {
                const float* p = Ab + (kb + 2 * akp[u]) * laK + i0 + aiv[u];
                ra[u].x = p[0]; ra[u].y = p[laK];
            }
            if (bKf) {
                rb[u] = *(const float2*)(Bb + (long)(j0 + bjv[u]) * lbJ + kb + 2 * bkp[u]);
            } else {
                const float* p = Bb + (kb + 2 * bkp[u]) * lbK + j0 + bjv[u];
                rb[u].x = p[0]; rb[u].y = p[lbK];
            }
        }
    };
    auto stage_store = [&](int buf) {
#pragma unroll
        for (int u = 0; u < 4; u++) {
            As[buf][akp[u] * 136 + aiv[u]] = packh2(ra[u].x, ra[u].y);
            Bs[buf][bkp[u] * 136 + bjv[u]] = packh2(rb[u].x, rb[u].y);
        }
    };

    stage_load(0);
    stage_store(0);
    __syncthreads();

    const int nkt = K / 16;
    for (int kt = 0; kt < nkt; kt++) {
        const int cur = kt & 1;
        const bool more = (kt + 1 < nkt);
        if (more) stage_load(kt + 1);

        const uint32_t* Ac = As[cur];
        const uint32_t* Bc = Bs[cur];
        uint32_t af[4][4], bf[4][2];
#pragma unroll
        for (int mi = 0; mi < 4; mi++) {
            int m0 = wm * 64 + mi * 16 + qrow;
            af[mi][0] = Ac[qcol * 136 + m0];
            af[mi][1] = Ac[qcol * 136 + m0 + 8];
            af[mi][2] = Ac[(qcol + 4) * 136 + m0];
            af[mi][3] = Ac[(qcol + 4) * 136 + m0 + 8];
        }
#pragma unroll
        for (int ni = 0; ni < 4; ni++) {
            int n0 = wn * 32 + ni * 8 + qrow;
            bf[ni][0] = Bc[qcol * 136 + n0];
            bf[ni][1] = Bc[(qcol + 4) * 136 + n0];
        }
#pragma unroll
        for (int mi = 0; mi < 4; mi++)
#pragma unroll
            for (int ni = 0; ni < 4; ni++) {
                asm volatile(
                    "mma.sync.aligned.m16n8k16.row.col.f32.f16.f16.f32 "
                    "{%0,%1,%2,%3}, {%4,%5,%6,%7}, {%8,%9}, {%0,%1,%2,%3};"
                    : "+f"(acc[mi][ni][0]), "+f"(acc[mi][ni][1]),
                      "+f"(acc[mi][ni][2]), "+f"(acc[mi][ni][3])
                    : "r"(af[mi][0]), "r"(af[mi][1]), "r"(af[mi][2]), "r"(af[mi][3]),
                      "r"(bf[ni][0]), "r"(bf[ni][1]));
            }

        if (more) {
            stage_store(cur ^ 1);
            __syncthreads();
        }
    }

    float* Cb = C + (long)blockIdx.z * sC;
    const float* Rb = resid ? (resid + (long)blockIdx.z * sC) : nullptr;
#pragma unroll
    for (int mi = 0; mi < 4; mi++) {
        int r0 = i0 + wm * 64 + mi * 16 + qrow;
        int r1 = r0 + 8;
        float s0 = 1.f, t0 = 0.f, s1 = 1.f, t1 = 0.f;
        if (epi >= 2) {
            float g = bnp[r0], bb = bnp[M + r0], m = bnp[2 * M + r0], vv = bnp[3 * M + r0];
            s0 = g * rsqrtf(vv + EPS); t0 = bb - m * s0;
            g = bnp[r1]; bb = bnp[M + r1]; m = bnp[2 * M + r1]; vv = bnp[3 * M + r1];
            s1 = g * rsqrtf(vv + EPS); t1 = bb - m * s1;
        }
#pragma unroll
        for (int ni = 0; ni < 4; ni++) {
            int cc = j0 + wn * 32 + ni * 8 + 2 * qcol;
            float y0 = acc[mi][ni][0], y1 = acc[mi][ni][1];
            float y2 = acc[mi][ni][2], y3 = acc[mi][ni][3];
            if (epi == 1) {
                y0 = (y0 >= 0.f) ? y0 : 0.2f * y0;
                y1 = (y1 >= 0.f) ? y1 : 0.2f * y1;
                y2 = (y2 >= 0.f) ? y2 : 0.2f * y2;
                y3 = (y3 >= 0.f) ? y3 : 0.2f * y3;
            } else if (epi == 2) {
                y0 = y0 * s0 + t0; y0 = (y0 >= 0.f) ? y0 : 0.2f * y0;
                y1 = y1 * s0 + t0; y1 = (y1 >= 0.f) ? y1 : 0.2f * y1;
                y2 = y2 * s1 + t1; y2 = (y2 >= 0.f) ? y2 : 0.2f * y2;
                y3 = y3 * s1 + t1; y3 = (y3 >= 0.f) ? y3 : 0.2f * y3;
            } else if (epi == 3) {
                float2 z0 = *(const float2*)(Rb + (long)r0 * ldc + cc);
                float2 z1 = *(const float2*)(Rb + (long)r1 * ldc + cc);
                y0 = (y0 + z0.x) * s0 + t0;
                y1 = (y1 + z0.y) * s0 + t0;
                y2 = (y2 + z1.x) * s1 + t1;
                y3 = (y3 + z1.y) * s1 + t1;
            }
            *(float2*)(Cb + (long)r0 * ldc + cc) = make_float2(y0, y1);
            *(float2*)(Cb + (long)r1 * ldc + cc) = make_float2(y2, y3);
        }
    }
}

// ---------------------------------------------------------------------------
// Dedicated fused Q/K/V GEMM: one launch, grid (16, 24, BB).
// sel = blockIdx.y>>3 picks weight/output; hot loop identical to gemm_f16
// with hardcoded shapes (M=N=K=1024, A K-contig, B i-contig, epi=0).
// ---------------------------------------------------------------------------
__global__ __launch_bounds__(256, 2)
void gemm_f16_qkv(const float* __restrict__ WQ, const float* __restrict__ WK,
                  const float* __restrict__ WV,
                  const float* __restrict__ H,
                  float* __restrict__ Q, float* __restrict__ Ko,
                  float* __restrict__ V)
{
    __shared__ uint32_t As[2][8 * 136];
    __shared__ uint32_t Bs[2][8 * 136];

    const int tid  = threadIdx.x;
    const int lane = tid & 31;
    const int w    = tid >> 5;
    const int wm   = w >> 2;
    const int wn   = w & 3;

    const int sel = blockIdx.y >> 3;
    const int i0  = (blockIdx.y & 7) * 128;
    const int j0  = blockIdx.x * 128;

    const float* Wsel = (sel == 0) ? WQ : (sel == 1) ? WK : WV;
    float* Csel = (sel == 0) ? Q : (sel == 1) ? Ko : V;

    const float* Ab = Wsel;                                   // (1024,1024) K-contig
    const float* Bb = H + (long)blockIdx.z * 1024 * NPTS;     // i-contig (lbK=NPTS... B[j][k]=H[k*NPTS+j])

    // A staging coords (K-contiguous), B staging coords (j-contiguous)
    int aiv[4], akp[4], bjv[4], bkp[4];
#pragma unroll
    for (int u = 0; u < 4; u++) {
        int q = u * 256 + tid;
        akp[u] = q & 7;  aiv[u] = q >> 3;     // aKf path
        bkp[u] = q >> 7; bjv[u] = q & 127;    // !bKf path
    }

    float acc[4][4][4];
#pragma unroll
    for (int mi = 0; mi < 4; mi++)
#pragma unroll
        for (int ni = 0; ni < 4; ni++)
#pragma unroll
            for (int r = 0; r < 4; r++) acc[mi][ni][r] = 0.f;

    const int qrow = lane >> 2;
    const int qcol = lane & 3;

    float2 ra[4], rb[4];
    auto stage_load = [&](int kt) {
        const long kb = (long)kt * 16;
#pragma unroll
        for (int u = 0; u < 4; u++) {
            ra[u] = *(const float2*)(Ab + (long)(i0 + aiv[u]) * 1024 + kb + 2 * akp[u]);
            const float* p = Bb + (kb + 2 * bkp[u]) * NPTS + j0 + bjv[u];
            rb[u].x = p[0]; rb[u].y = p[NPTS];
        }
    };
    auto stage_store = [&](int buf) {
#pragma unroll
        for (int u = 0; u < 4; u++) {
            As[buf][akp[u] * 136 + aiv[u]] = packh2(ra[u].x, ra[u].y);
            Bs[buf][bkp[u] * 136 + bjv[u]] = packh2(rb[u].x, rb[u].y);
        }
    };

    stage_load(0);
    stage_store(0);
    __syncthreads();

    const int nkt = 1024 / 16;
    for (int kt = 0; kt < nkt; kt++) {
        const int cur = kt & 1;
        const bool more = (kt + 1 < nkt);
        if (more) stage_load(kt + 1);

        const uint32_t* Ac = As[cur];
        const uint32_t* Bc = Bs[cur];
        uint32_t af[4][4], bf[4][2];
#pragma unroll
        for (int mi = 0; mi < 4; mi++) {
            int m0 = wm * 64 + mi * 16 + qrow;
            af[mi][0] = Ac[qcol * 136 + m0];
            af[mi][1] = Ac[qcol * 136 + m0 + 8];
            af[mi][2] = Ac[(qcol + 4) * 136 + m0];
            af[mi][3] = Ac[(qcol + 4) * 136 + m0 + 8];
        }
#pragma unroll
        for (int ni = 0; ni < 4; ni++) {
            int n0 = wn * 32 + ni * 8 + qrow;
            bf[ni][0] = Bc[qcol * 136 + n0];
            bf[ni][1] = Bc[(qcol + 4) * 136 + n0];
        }
#pragma unroll
        for (int mi = 0; mi < 4; mi++)
#pragma unroll
            for (int ni = 0; ni < 4; ni++) {
                asm volatile(
                    "mma.sync.aligned.m16n8k16.row.col.f32.f16.f16.f32 "
                    "{%0,%1,%2,%3}, {%4,%5,%6,%7}, {%8,%9}, {%0,%1,%2,%3};"
                    : "+f"(acc[mi][ni][0]), "+f"(acc[mi][ni][1]),
                      "+f"(acc[mi][ni][2]), "+f"(acc[mi][ni][3])
                    : "r"(af[mi][0]), "r"(af[mi][1]), "r"(af[mi][2]), "r"(af[mi][3]),
                      "r"(bf[ni][0]), "r"(bf[ni][1]));
            }

        if (more) {
            stage_store(cur ^ 1);
            __syncthreads();
        }
    }

    float* Cb = Csel + (long)blockIdx.z * 1024 * NPTS;
#pragma unroll
    for (int mi = 0; mi < 4; mi++) {
        int r0 = i0 + wm * 64 + mi * 16 + qrow;
        int r1 = r0 + 8;
#pragma unroll
        for (int ni = 0; ni < 4; ni++) {
            int cc = j0 + wn * 32 + ni * 8 + 2 * qcol;
            *(float2*)(Cb + (long)r0 * NPTS + cc) =
                make_float2(acc[mi][ni][0], acc[mi][ni][1]);
            *(float2*)(Cb + (long)r1 * NPTS + cc) =
                make_float2(acc[mi][ni][2], acc[mi][ni][3]);
        }
    }
}

// ---------------------------------------------------------------------------
// fp32 SGEMM (kNN dot products — selection is tie-sensitive, stays fp32)
// ---------------------------------------------------------------------------
__global__ void gemm128(const float* __restrict__ A, const float* __restrict__ B,
                        float* __restrict__ C,
                        int M, int N, int K,
                        long laI, long laK, long sA,
                        long lbJ, long lbK, long sB,
                        long ldc, long sC)
{
    __shared__ float4 As4[8 * 33];
    __shared__ float4 Bs4[8 * 33];
    float* As = (float*)As4;
    float* Bs = (float*)Bs4;

    const int tid = threadIdx.x;
    const int tx  = tid & 15;
    const int ty  = tid >> 4;
    const int i0  = blockIdx.y * 128;
    const int j0  = blockIdx.x * 128;

    const float* Ab = A + (long)blockIdx.z * sA;
    const float* Bb = B + (long)blockIdx.z * sB;

    const bool aKfast = (laK == 1);
    const bool bKfast = (lbK == 1);

    float acc[8][8];
#pragma unroll
    for (int r = 0; r < 8; r++)
#pragma unroll
        for (int c = 0; c < 8; c++) acc[r][c] = 0.f;

    for (int k0 = 0; k0 < K; k0 += 8) {
#pragma unroll
        for (int u = 0; u < 4; u++) {
            int l = tid + u * 256;
            int i, k;
            if (aKfast) { i = l >> 3; k = l & 7; }
            else        { i = l & 127; k = l >> 7; }
            int kg = k0 + k;
            float v = 0.f;
            if (kg < K) v = Ab[(long)(i0 + i) * laI + (long)kg * laK];
            As[k * 132 + i] = v;
        }
#pragma unroll
        for (int u = 0; u < 4; u++) {
            int l = tid + u * 256;
            int j, k;
            if (bKfast) { j = l >> 3; k = l & 7; }
            else        { j = l & 127; k = l >> 7; }
            int kg = k0 + k;
            float v = 0.f;
            if (kg < K) v = Bb[(long)(j0 + j) * lbJ + (long)kg * lbK];
            Bs[k * 132 + j] = v;
        }
        __syncthreads();

#pragma unroll
        for (int kk = 0; kk < 8; kk++) {
            const float4* Ar = (const float4*)(As + kk * 132);
            const float4* Br = (const float4*)(Bs + kk * 132);
            float4 a0 = Ar[ty * 2], a1 = Ar[ty * 2 + 1];
            float4 b0 = Br[tx * 2], b1 = Br[tx * 2 + 1];
            float av[8] = {a0.x, a0.y, a0.z, a0.w, a1.x, a1.y, a1.z, a1.w};
            float bv[8] = {b0.x, b0.y, b0.z, b0.w, b1.x, b1.y, b1.z, b1.w};
#pragma unroll
            for (int r = 0; r < 8; r++)
#pragma unroll
                for (int c = 0; c < 8; c++)
                    acc[r][c] += av[r] * bv[c];
        }
        __syncthreads();
    }

    float* Cb = C + (long)blockIdx.z * sC;
#pragma unroll
    for (int r = 0; r < 8; r++) {
        int ig = i0 + ty * 8 + r;
        float4* dst = (float4*)(Cb + (long)ig * ldc + (j0 + tx * 8));
        dst[0] = make_float4(acc[r][0], acc[r][1], acc[r][2], acc[r][3]);
        dst[1] = make_float4(acc[r][4], acc[r][5], acc[r][6], acc[r][7]);
    }
}

// ---------------------------------------------------------------------------
// Squared norm per point
// ---------------------------------------------------------------------------
__global__ void sqnorm_k(const float* __restrict__ f, float* __restrict__ sq,
                         int C, long bstride)
{
    int n = blockIdx.x * blockDim.x + threadIdx.x;
    int b = blockIdx.y;
    if (n >= NPTS) return;
    const float* fb = f + (long)b * bstride;
    float s = 0.f;
    for (int c = 0; c < C; c++) {
        float v = fb[(long)c * NPTS + n];
        s += v * v;
    }
    sq[(long)b * NPTS + n] = s;
}

// ---------------------------------------------------------------------------
// Feature transpose: ft[b][n][c] = f[b][c][n]  (only for 3-ch layer-1 input)
// ---------------------------------------------------------------------------
__global__ void transpose_k(const float* __restrict__ f, long fBS, int C,
                            float* __restrict__ ft)
{
    int n = blockIdx.x * 256 + threadIdx.x;
    int c = blockIdx.y, b = blockIdx.z;
    ft[((long)b * NPTS + n) * C + c] = f[(long)b * fBS + (long)c * NPTS + n];
}

// ---------------------------------------------------------------------------
// Top-K (32 smallest), warp-per-row, smem key cache (R16, best)
// ---------------------------------------------------------------------------
__global__ __launch_bounds__(256)
void topk_w(const float* __restrict__ dot, const float* __restrict__ sq,
            int* __restrict__ idx)
{
    extern __shared__ float skey[];
    const int lane = threadIdx.x & 31;
    const int wid  = threadIdx.x >> 5;
    const int n = blockIdx.x * 8 + wid;
    const int b = blockIdx.y;
    float* key = skey + wid * NPTS;
    const float* drow = dot + ((long)b * NPTS + n) * NPTS;
    const float* sqb  = sq + (long)b * NPTS;

    unsigned long long cmin[8];
#pragma unroll
    for (int ch = 0; ch < 8; ch++) cmin[ch] = ~0ull;

    float4 dv[16];
#pragma unroll
    for (int t16 = 0; t16 < 16; t16++)
        dv[t16] = *(const float4*)(drow + t16 * 128 + lane * 4);

#pragma unroll
    for (int t16 = 0; t16 < 16; t16++) {
        int m0 = t16 * 128 + lane * 4;
        float4 sv = *(const float4*)(sqb + m0);
        float v0 = sv.x - 2.f * dv[t16].x;
        float v1 = sv.y - 2.f * dv[t16].y;
        float v2 = sv.z - 2.f * dv[t16].z;
        float v3 = sv.w - 2.f * dv[t16].w;
        *(float4*)(key + m0) = make_float4(v0, v1, v2, v3);
        int ch = t16 >> 1;
        unsigned long long k0 = packkey(v0, m0);
        unsigned long long k1 = packkey(v1, m0 + 1);
        unsigned long long k2 = packkey(v2, m0 + 2);
        unsigned long long k3 = packkey(v3, m0 + 3);
        if (k1 < k0) k0 = k1;
        if (k3 < k2) k2 = k3;
        if (k2 < k0) k0 = k2;
        if (k0 < cmin[ch]) cmin[ch] = k0;
    }
    unsigned long long laneMin = cmin[0];
#pragma unroll
    for (int ch = 1; ch < 8; ch++) if (cmin[ch] < laneMin) laneMin = cmin[ch];

    int* orow = idx + ((long)b * NPTS + n) * KNN;
    for (int it = 0; it < KNN; it++) {
        unsigned long long r = laneMin;
#pragma unroll
        for (int off = 16; off; off >>= 1) {
            unsigned long long o = __shfl_xor_sync(0xffffffffu, r, off);
            if (o < r) r = o;
        }
        int ri = (int)(uint32_t)r;
        if (lane == 0) orow[it] = ri;
        if (lane == ((ri >> 2) & 31)) {
            key[ri] = 3.4e38f;
            int ch = ri >> 8;
            unsigned long long nm = ~0ull;
#pragma unroll
            for (int t2 = 0; t2 < 2; t2++) {
                int m0 = (ch * 2 + t2) * 128 + lane * 4;
                float4 kv = *(const float4*)(key + m0);
                unsigned long long k0 = packkey(kv.x, m0);
                unsigned long long k1 = packkey(kv.y, m0 + 1);
                unsigned long long k2 = packkey(kv.z, m0 + 2);
                unsigned long long k3 = packkey(kv.w, m0 + 3);
                if (k1 < k0) k0 = k1;
                if (k3 < k2) k2 = k3;
                if (k2 < k0) k0 = k2;
                if (k0 < nm) nm = k0;
            }
            cmin[ch] = nm;
            laneMin = cmin[0];
#pragma unroll
            for (int c2 = 1; c2 < 8; c2++) if (cmin[c2] < laneMin) laneMin = cmin[c2];
        }
        __syncwarp();
    }
}

// ---------------------------------------------------------------------------
// Fused EdgeConv, 16 points/block + optional dual-write into DISJOINT
// point-major ft buffer (R15, passing)
// ---------------------------------------------------------------------------
template<int CIN>
__global__ __launch_bounds__(256)
void edgeconv_p(const float* __restrict__ f, long fBS,
                const float* __restrict__ ft,
                const int* __restrict__ idxg,
                const float* __restrict__ w1, const float* __restrict__ bn1,
                const float* __restrict__ w2, const float* __restrict__ bn2,
                float* __restrict__ out, long oBS,
                float* __restrict__ ftOut)
{
    constexpr int CP = CIN + 1;
    extern __shared__ float sm[];
    float* W1A  = sm;
    float* W1D  = W1A + CIN * 64;
    float* W2S  = W1D + CIN * 64;
    float* BN   = W2S + 4096;
    float* CTR  = BN + 256;
    float* US   = CTR + CIN * 16;
    int*   IDS  = (int*)(US + 1024);
    float* BUFA = (float*)(IDS + 512);
    float* BUFH = BUFA + 2 * 32 * CP;

    const int tid = threadIdx.x;
    const int n0 = blockIdx.x * 16;
    const int b  = blockIdx.y;
    const float* fb  = f + (long)b * fBS;
    const float* ftb = ft + (long)b * NPTS * CIN;

    for (int l = tid; l < CIN * 64; l += 256) {
        int o = l & 63, c = l >> 6;
        float a = w1[o * (2 * CIN) + c];
        W1A[c * 64 + o] = a;
        W1D[c * 64 + o] = w1[o * (2 * CIN) + CIN + c] - a;
    }
    for (int l = tid; l < 4096; l += 256) {
        int o = l & 63, c = l >> 6;
        W2S[c * 64 + o] = w2[o * 64 + c];
    }
    if (tid < 64) {
        float g = bn1[tid], bb = bn1[64 + tid], m = bn1[128 + tid], vv = bn1[192 + tid];
        float s = g * rsqrtf(vv + EPS);
        BN[tid] = s; BN[64 + tid] = bb - m * s;
        g = bn2[tid]; bb = bn2[64 + tid]; m = bn2[128 + tid]; vv = bn2[192 + tid];
        s = g * rsqrtf(vv + EPS);
        BN[128 + tid] = s; BN[192 + tid] = bb - m * s;
    }
    for (int l = tid; l < CIN * 16; l += 256) {
        int c = l >> 4, p = l & 15;
        CTR[c * 16 + p] = fb[(long)c * NPTS + n0 + p];
    }
    for (int l = tid; l < 512; l += 256)
        IDS[l] = idxg[((long)b * NPTS + n0 + (l >> 5)) * KNN + (l & 31)];
    __syncthreads();

#pragma unroll
    for (int r = 0; r < 4; r++) {
        int q = tid + 256 * r;
        int p = q >> 6, o = q & 63;
        float a = 0.f;
        for (int c = 0; c < CIN; c++)
            a += W1D[c * 64 + o] * CTR[c * 16 + p];
        US[p * 64 + o] = a;
    }

    auto gather = [&](int p, int buf) {
        float* dst = BUFA + buf * 32 * CP;
        if (CIN == 64) {
            for (int l = tid; l < 2048; l += 256) {
                int k = l >> 6, c = l & 63;
                dst[k * CP + c] = ftb[(long)IDS[p * 32 + k] * 64 + c];
            }
        } else {
            for (int l = tid; l < 32 * CIN; l += 256) {
                int k = l / CIN, c = l % CIN;
                dst[k * CP + c] = ftb[(long)IDS[p * 32 + k] * CIN + c];
            }
        }
    };
    gather(0, 0);
    __syncthreads();

    const int k  = tid & 31;
    const int og = tid >> 5;
    float* ob = out + (long)b * oBS;
    float* fo = ftOut ? (ftOut + (long)b * NPTS * 64) : nullptr;

    for (int p = 0; p < 16; p++) {
        const int cur = p & 1;
        const float* A = BUFA + cur * 32 * CP + k * CP;

        float acc[8];
#pragma unroll
        for (int j = 0; j < 8; j++) acc[j] = 0.f;
        for (int c = 0; c < CIN; c++) {
            float nv = A[c];
#pragma unroll
            for (int j = 0; j < 8; j++)
                acc[j] += W1A[c * 64 + og * 8 + j] * nv;
        }
#pragma unroll
        for (int j = 0; j < 8; j++) {
            int o = og * 8 + j;
            float y = (acc[j] + US[p * 64 + o]) * BN[o] + BN[64 + o];
            BUFH[k * 65 + o] = (y >= 0.f) ? y : 0.2f * y;
        }
        if (p + 1 < 16) gather(p + 1, cur ^ 1);
        __syncthreads();

        float acc2[8];
#pragma unroll
        for (int j = 0; j < 8; j++) acc2[j] = 0.f;
        for (int c = 0; c < 64; c++) {
            float hv = BUFH[k * 65 + c];
#pragma unroll
            for (int j = 0; j < 8; j++)
                acc2[j] += W2S[c * 64 + og * 8 + j] * hv;
        }
        float yout[8];
#pragma unroll
        for (int j = 0; j < 8; j++) {
            int o = og * 8 + j;
            float y = acc2[j] * BN[128 + o] + BN[192 + o];
            y = (y >= 0.f) ? y : 0.2f * y;
#pragma unroll
            for (int off = 16; off; off >>= 1)
                y = fmaxf(y, __shfl_xor_sync(0xffffffffu, y, off));
            yout[j] = y;
            if (k == 0) ob[(long)o * NPTS + n0 + p] = y;
        }
        if (fo && k == 0) {
            float4* dst = (float4*)(fo + (long)(n0 + p) * 64 + og * 8);
            dst[0] = make_float4(yout[0], yout[1], yout[2], yout[3]);
            dst[1] = make_float4(yout[4], yout[5], yout[6], yout[7]);
        }
        __syncthreads();
    }
}

// ---------------------------------------------------------------------------
// Row softmax, single read + single write (R7, passing)
// ---------------------------------------------------------------------------
__global__ __launch_bounds__(256)
void softmax_s(float* __restrict__ S)
{
    __shared__ float red[8];
    const int tid = threadIdx.x, lane = tid & 31, wid = tid >> 5;
    float* row = S + ((long)blockIdx.y * NPTS + blockIdx.x) * NPTS;
    const float scale = 0.03125f;

    float4 v0 = *(float4*)(row + tid * 8);
    float4 v1 = *(float4*)(row + tid * 8 + 4);
    float mx = fmaxf(fmaxf(fmaxf(v0.x, v0.y), fmaxf(v0.z, v0.w)),
                     fmaxf(fmaxf(v1.x, v1.y), fmaxf(v1.z, v1.w)));
#pragma unroll
    for (int off = 16; off; off >>= 1)
        mx = fmaxf(mx, __shfl_xor_sync(0xffffffffu, mx, off));
    if (lane == 0) red[wid] = mx;
    __syncthreads();
    mx = fmaxf(fmaxf(fmaxf(red[0], red[1]), fmaxf(red[2], red[3])),
               fmaxf(fmaxf(red[4], red[5]), fmaxf(red[6], red[7])));
    __syncthreads();

    v0.x = __expf((v0.x - mx) * scale); v0.y = __expf((v0.y - mx) * scale);
    v0.z = __expf((v0.z - mx) * scale); v0.w = __expf((v0.w - mx) * scale);
    v1.x = __expf((v1.x - mx) * scale); v1.y = __expf((v1.y - mx) * scale);
    v1.z = __expf((v1.z - mx) * scale); v1.w = __expf((v1.w - mx) * scale);
    float sum = v0.x + v0.y + v0.z + v0.w + v1.x + v1.y + v1.z + v1.w;
#pragma unroll
    for (int off = 16; off; off >>= 1)
        sum += __shfl_xor_sync(0xffffffffu, sum, off);
    if (lane == 0) red[wid] = sum;
    __syncthreads();
    sum = red[0] + red[1] + red[2] + red[3] + red[4] + red[5] + red[6] + red[7];
    float inv = 1.f / sum;

    v0.x *= inv; v0.y *= inv; v0.z *= inv; v0.w *= inv;
    v1.x *= inv; v1.y *= inv; v1.z *= inv; v1.w *= inv;
    *(float4*)(row + tid * 8)     = v0;
    *(float4*)(row + tid * 8 + 4) = v1;
}

// ---------------------------------------------------------------------------
// Launch
// ---------------------------------------------------------------------------
static inline int ec_smem(int cin) {
    return (2 * cin * 64 + 4096 + 256 + cin * 16 + 1024) * 4
         + 512 * 4
         + (2 * 32 * (cin + 1) + 32 * 65) * 4;
}

extern "C" void kernel_launch(void* const* d_in, const int* in_sizes, int n_in,
                              void* d_out, int out_size)
{
    const float* x      = (const float*)d_in[0];
    const float* ec1_w1 = (const float*)d_in[1];
    const float* ec1_b1 = (const float*)d_in[2];
    const float* ec1_w2 = (const float*)d_in[3];
    const float* ec1_b2 = (const float*)d_in[4];
    const float* ec2_w1 = (const float*)d_in[5];
    const float* ec2_b1 = (const float*)d_in[6];
    const float* ec2_w2 = (const float*)d_in[7];
    const float* ec2_b2 = (const float*)d_in[8];
    const float* ec3_w1 = (const float*)d_in[9];
    const float* ec3_b1 = (const float*)d_in[10];
    const float* ec3_w2 = (const float*)d_in[11];
    const float* ec3_b2 = (const float*)d_in[12];
    const float* emb_w  = (const float*)d_in[13];
    const float* q_w    = (const float*)d_in[14];
    const float* k_w    = (const float*)d_in[15];
    const float* v_w    = (const float*)d_in[16];
    const float* attb1  = (const float*)d_in[17];
    const float* ff_w1  = (const float*)d_in[18];
    const float* ff_w2  = (const float*)d_in[19];
    const float* attb2  = (const float*)d_in[20];
    const float* cb_w   = (const float*)d_in[21];
    const float* cb_bn  = (const float*)d_in[22];

    float *p_dot, *p_sq, *p_xc, *p_ft, *p_h, *p_q, *p_k, *p_v, *p_ff1;
    int* p_idx;
    cudaGetSymbolAddress((void**)&p_dot, g_dot);
    cudaGetSymbolAddress((void**)&p_sq,  g_sq);
    cudaGetSymbolAddress((void**)&p_idx, g_idx);
    cudaGetSymbolAddress((void**)&p_xc,  g_xc);
    cudaGetSymbolAddress((void**)&p_ft,  g_ft);
    cudaGetSymbolAddress((void**)&p_h,   g_h);
    cudaGetSymbolAddress((void**)&p_q,   g_q);
    cudaGetSymbolAddress((void**)&p_k,   g_k);
    cudaGetSymbolAddress((void**)&p_v,   g_v);
    cudaGetSymbolAddress((void**)&p_ff1, g_ff1);

    // disjoint point-major feature slabs carved from g_h (emb overwrites later)
    float* ft64_a = p_h;
    float* ft64_b = p_h + (long)BB * NPTS * 64;

    static bool attr_done = false;
    if (!attr_done) {
        cudaFuncSetAttribute(topk_w, cudaFuncAttributeMaxDynamicSharedMemorySize,
                             8 * NPTS * 4);
        cudaFuncSetAttribute(edgeconv_p<3>, cudaFuncAttributeMaxDynamicSharedMemorySize,
                             ec_smem(3));
        cudaFuncSetAttribute(edgeconv_p<64>, cudaFuncAttributeMaxDynamicSharedMemorySize,
                             ec_smem(64));
        attr_done = true;
    }

    const long NN2 = (long)NPTS * NPTS;
    dim3 gSq(NPTS / 256, BB), bSq(256);
    dim3 gRow(NPTS, BB), bRow(256);
    dim3 gTopk(NPTS / 8, BB);
    dim3 gEc(NPTS / 16, BB);
    const int smemTopk = 8 * NPTS * 4;

    // ---- EdgeConv 1 (CIN=3): reads p_ft(3ch), dual-writes ft64_a ----
    sqnorm_k<<<gSq, bSq>>>(x, p_sq, 3, (long)3 * NPTS);
    gemm128<<<dim3(16, 16, BB), 256>>>(x, x, p_dot, NPTS, NPTS, 3,
                                       1, NPTS, (long)3 * NPTS,
                                       1, NPTS, (long)3 * NPTS,
                                       NPTS, NN2);
    transpose_k<<<dim3(NPTS / 256, 3, BB), 256>>>(x, (long)3 * NPTS, 3, p_ft);
    topk_w<<<gTopk, 256, smemTopk>>>(p_dot, p_sq, p_idx);
    edgeconv_p<3><<<gEc, 256, ec_smem(3)>>>(x, (long)3 * NPTS, p_ft, p_idx,
                                            ec1_w1, ec1_b1, ec1_w2, ec1_b2,
                                            p_xc, (long)192 * NPTS, ft64_a);

    // ---- EdgeConv 2 (CIN=64): reads ft64_a, dual-writes ft64_b ----
    sqnorm_k<<<gSq, bSq>>>(p_xc, p_sq, 64, (long)192 * NPTS);
    gemm128<<<dim3(16, 16, BB), 256>>>(p_xc, p_xc, p_dot, NPTS, NPTS, 64,
                                       1, NPTS, (long)192 * NPTS,
                                       1, NPTS, (long)192 * NPTS,
                                       NPTS, NN2);
    topk_w<<<gTopk, 256, smemTopk>>>(p_dot, p_sq, p_idx);
    edgeconv_p<64><<<gEc, 256, ec_smem(64)>>>(p_xc, (long)192 * NPTS, ft64_a, p_idx,
                                              ec2_w1, ec2_b1, ec2_w2, ec2_b2,
                                              p_xc + (long)64 * NPTS,
                                              (long)192 * NPTS, ft64_b);

    // ---- EdgeConv 3 (CIN=64): reads ft64_b ----
    sqnorm_k<<<gSq, bSq>>>(p_xc + (long)64 * NPTS, p_sq, 64, (long)192 * NPTS);
    gemm128<<<dim3(16, 16, BB), 256>>>(p_xc + (long)64 * NPTS, p_xc + (long)64 * NPTS,
                                       p_dot, NPTS, NPTS, 64,
                                       1, NPTS, (long)192 * NPTS,
                                       1, NPTS, (long)192 * NPTS,
                                       NPTS, NN2);
    topk_w<<<gTopk, 256, smemTopk>>>(p_dot, p_sq, p_idx);
    edgeconv_p<64><<<gEc, 256, ec_smem(64)>>>(p_xc + (long)64 * NPTS, (long)192 * NPTS,
                                              ft64_b, p_idx,
                                              ec3_w1, ec3_b1, ec3_w2, ec3_b2,
                                              p_xc + (long)128 * NPTS,
                                              (long)192 * NPTS, nullptr);

    // ---- emb: h = emb_w (1024x192) @ xc  (overwrites ft64 scratch in g_h) ----
    gemm_f16<<<dim3(16, 8, BB), 256>>>(emb_w, p_xc, p_h, 1024, NPTS, 192,
                                       192, 1, 0,
                                       1, NPTS, (long)192 * NPTS,
                                       NPTS, (long)1024 * NPTS, 0, nullptr, nullptr);

    // ---- q, k, v: single fused launch (dedicated kernel, prologue select) ----
    gemm_f16_qkv<<<dim3(16, 24, BB), 256>>>(q_w, k_w, v_w, p_h, p_q, p_k, p_v);

    // ---- scores = q^T k ----
    gemm_f16<<<dim3(16, 16, BB), 256>>>(p_q, p_k, p_dot, NPTS, NPTS, 1024,
                                        1, NPTS, (long)1024 * NPTS,
                                        1, NPTS, (long)1024 * NPTS,
                                        NPTS, NN2, 0, nullptr, nullptr);
    softmax_s<<<gRow, bRow>>>(p_dot);

    // ---- h = bn(h + att @ v, att_bn1) ----
    gemm_f16<<<dim3(16, 8, BB), 256>>>(p_v, p_dot, p_h, 1024, NPTS, NPTS,
                                       NPTS, 1, (long)1024 * NPTS,
                                       NPTS, 1, NN2,
                                       NPTS, (long)1024 * NPTS, 3, attb1, p_h);

    // ---- ff1 = lrelu(ff_w1 @ h) ----
    gemm_f16<<<dim3(16, 4, BB), 256>>>(ff_w1, p_h, p_ff1, 512, NPTS, 1024,
                                       1024, 1, 0,
                                       1, NPTS, (long)1024 * NPTS,
                                       NPTS, (long)512 * NPTS, 1, nullptr, nullptr);

    // ---- h = bn(h + ff_w2 @ ff1, att_bn2) ----
    gemm_f16<<<dim3(16, 8, BB), 256>>>(ff_w2, p_ff1, p_h, 1024, NPTS, 512,
                                       512, 1, 0,
                                       1, NPTS, (long)512 * NPTS,
                                       NPTS, (long)1024 * NPTS, 3, attb2, p_h);

    // ---- out = lrelu(bn(cb_w @ h, cb_bn)) -> d_out ----
    gemm_f16<<<dim3(16, 8, BB), 256>>>(cb_w, p_h, (float*)d_out, 1024, NPTS, 1024,
                                       1024, 1, 0,
                                       1, NPTS, (long)1024 * NPTS,
                                       NPTS, (long)1024 * NPTS, 2, cb_bn, nullptr);
}